// round 8
// baseline (speedup 1.0000x reference)
#include <cuda_runtime.h>
#include <cuda_bf16.h>
#include <math.h>
#include <stdint.h>

#define BB 2
#define TT 2048
#define DD 1024
#define HH 16
#define LL 8
#define II 4096
#define MROWS (BB*TT)          // 4096
#define MASK_BIAS (-10000.0f)

// -------- scratch (no allocations allowed) --------
static __device__ float g_H  [(size_t)MROWS*DD];          // residual stream (f32)
static __device__ __nv_bfloat16 g_Ah[(size_t)MROWS*II];   // activation split hi (X / CTX)
static __device__ __nv_bfloat16 g_Al[(size_t)MROWS*II];   // activation split lo
static __device__ __nv_bfloat16 g_Fh[(size_t)MROWS*II];   // FF / QKV split hi
static __device__ __nv_bfloat16 g_Fl[(size_t)MROWS*II];   // FF / QKV split lo
static __device__ __nv_bfloat16 g_Wh[(size_t)II*DD];      // weight^T split hi [N x K]
static __device__ __nv_bfloat16 g_Wl[(size_t)II*DD];      // weight^T split lo

// ---------------------------------------------------------------- helpers
__device__ __forceinline__ uint32_t smem_u32(const void* p) {
    return (uint32_t)__cvta_generic_to_shared(p);
}

__device__ __forceinline__ void split_bf16(float x, __nv_bfloat16& h, __nv_bfloat16& l) {
    h = __float2bfloat16(x);
    l = __float2bfloat16(x - __bfloat162float(h));
}

__device__ __forceinline__ void mma_bf16(float* c, const uint32_t* a, const uint32_t* b) {
    asm volatile(
        "mma.sync.aligned.m16n8k16.row.col.f32.bf16.bf16.f32 "
        "{%0,%1,%2,%3},{%4,%5,%6,%7},{%8,%9},{%0,%1,%2,%3};"
        : "+f"(c[0]), "+f"(c[1]), "+f"(c[2]), "+f"(c[3])
        : "r"(a[0]), "r"(a[1]), "r"(a[2]), "r"(a[3]), "r"(b[0]), "r"(b[1]));
}

__device__ __forceinline__ void cpasync16(uint32_t dst, const void* src) {
    asm volatile("cp.async.cg.shared.global [%0], [%1], 16;" :: "r"(dst), "l"(src));
}
__device__ __forceinline__ void cp_commit() { asm volatile("cp.async.commit_group;"); }
__device__ __forceinline__ void cp_wait1()  { asm volatile("cp.async.wait_group 1;"); }
__device__ __forceinline__ void cp_wait0()  { asm volatile("cp.async.wait_group 0;"); }

__device__ __forceinline__ void ldmx4_trans(uint32_t* r, uint32_t saddr) {
    asm volatile("ldmatrix.sync.aligned.m8n8.x4.trans.shared.b16 {%0,%1,%2,%3}, [%4];"
        : "=r"(r[0]), "=r"(r[1]), "=r"(r[2]), "=r"(r[3]) : "r"(saddr));
}

__device__ __forceinline__ uint32_t pack_bf16(float x, float y) {
    __nv_bfloat162 v = __float22bfloat162_rn(float2{x, y});
    return *(uint32_t*)&v;
}

// ---------------------------------------------------------------- copy
__global__ void copy_kernel(const float4* __restrict__ src, float4* __restrict__ dst, int n4) {
    int i = blockIdx.x * blockDim.x + threadIdx.x;
    if (i < n4) dst[i] = src[i];
}

// ---------------------------------------------------------------- layernorm core (256 thr, D=1024)
__device__ __forceinline__ float4 ln_core(const float* __restrict__ in,
                                          const float* __restrict__ w,
                                          const float* __restrict__ bsc, int row, int t) {
    const float4* x4 = (const float4*)(in + (size_t)row * DD);
    float4 v = x4[t];
    float s = v.x + v.y + v.z + v.w;
    float q = v.x*v.x + v.y*v.y + v.z*v.z + v.w*v.w;
    #pragma unroll
    for (int o = 16; o; o >>= 1) {
        s += __shfl_xor_sync(0xffffffffu, s, o);
        q += __shfl_xor_sync(0xffffffffu, q, o);
    }
    __shared__ float ss[8], sq[8];
    __shared__ float red[2];
    int wid = t >> 5, lane = t & 31;
    if (lane == 0) { ss[wid] = s; sq[wid] = q; }
    __syncthreads();
    if (t == 0) {
        float S = 0.f, Q = 0.f;
        #pragma unroll
        for (int i = 0; i < 8; i++) { S += ss[i]; Q += sq[i]; }
        float mean = S * (1.0f / DD);
        float var  = Q * (1.0f / DD) - mean * mean;
        red[0] = mean;
        red[1] = rsqrtf(var + 1e-5f);
    }
    __syncthreads();
    float mean = red[0], inv = red[1];
    float4 wv = ((const float4*)w)[t];
    float4 bv = ((const float4*)bsc)[t];
    float4 o;
    o.x = (v.x - mean) * inv * wv.x + bv.x;
    o.y = (v.y - mean) * inv * wv.y + bv.y;
    o.z = (v.z - mean) * inv * wv.z + bv.z;
    o.w = (v.w - mean) * inv * wv.w + bv.w;
    return o;
}

__global__ void ln_kernel(const float* __restrict__ in, const float* __restrict__ w,
                          const float* __restrict__ bsc, float* __restrict__ out) {
    int row = blockIdx.x, t = threadIdx.x;
    float4 o = ln_core(in, w, bsc, row, t);
    ((float4*)(out + (size_t)row * DD))[t] = o;
}

__global__ void ln_split_kernel(const float* __restrict__ in, const float* __restrict__ w,
                                const float* __restrict__ bsc,
                                __nv_bfloat16* __restrict__ oh, __nv_bfloat16* __restrict__ ol) {
    int row = blockIdx.x, t = threadIdx.x;
    float4 o = ln_core(in, w, bsc, row, t);
    __nv_bfloat16 h0,h1,h2,h3,l0,l1,l2,l3;
    split_bf16(o.x,h0,l0); split_bf16(o.y,h1,l1); split_bf16(o.z,h2,l2); split_bf16(o.w,h3,l3);
    size_t idx = (size_t)row * DD + t * 4;
    *(__nv_bfloat162*)(oh + idx)     = __nv_bfloat162{h0,h1};
    *(__nv_bfloat162*)(oh + idx + 2) = __nv_bfloat162{h2,h3};
    *(__nv_bfloat162*)(ol + idx)     = __nv_bfloat162{l0,l1};
    *(__nv_bfloat162*)(ol + idx + 2) = __nv_bfloat162{l2,l3};
}

// ---------------------------------------------------------------- weight transpose + split
// W: [K x N] f32 row-major  ->  Th/Tl: [N x K] bf16
__global__ void splitT_kernel(const float* __restrict__ W, __nv_bfloat16* __restrict__ Th,
                              __nv_bfloat16* __restrict__ Tl, int K, int N) {
    __shared__ float t[32][33];
    int k0 = blockIdx.y * 32, n0 = blockIdx.x * 32;
    int tx = threadIdx.x & 31, ty = threadIdx.x >> 5;   // 8 rows per pass
    #pragma unroll
    for (int i = 0; i < 4; i++) {
        int r = ty + i * 8;
        t[r][tx] = W[(size_t)(k0 + r) * N + n0 + tx];
    }
    __syncthreads();
    #pragma unroll
    for (int i = 0; i < 4; i++) {
        int r = ty + i * 8;
        float v = t[tx][r];                 // = W[k0+tx][n0+r]
        __nv_bfloat16 h, l;
        split_bf16(v, h, l);
        size_t o = (size_t)(n0 + r) * K + k0 + tx;
        Th[o] = h; Tl[o] = l;
    }
}

// ---------------------------------------------------------------- bf16x3 mma.sync GEMM
// C[m][n] = sum_k A[m][k]*W[k][n] + bias (+res)(+relu). B operand = W^T [N x K] bf16.
// CTA 128x128, BK=64, 8 warps (2x4), warp tile 64x32, double-buffered cp.async.
#define SROWB   144                       // bytes per smem row (64 bf16 + 8 pad)
#define TILEB   (128 * SROWB)             // 18432 B
#define STAGEB  (4 * TILEB)               // Ah, Al, Bh, Bl
#define GSMEM   (2 * STAGEB)              // 147456 B

template<bool RES, bool RELU, bool SPLITOUT>
__global__ __launch_bounds__(256)
void gemm_mma(const __nv_bfloat16* __restrict__ Ah, const __nv_bfloat16* __restrict__ Al,
              const __nv_bfloat16* __restrict__ Bh, const __nv_bfloat16* __restrict__ Bl,
              const float* __restrict__ bias, const float* __restrict__ res,
              float* __restrict__ C, __nv_bfloat16* __restrict__ Ch, __nv_bfloat16* __restrict__ Cl,
              int N, int K) {
    extern __shared__ char sm[];
    const int tid = threadIdx.x, lane = tid & 31, wid = tid >> 5;
    const int g = lane >> 2, t = lane & 3;
    const int warpM = (wid >> 2) * 64, warpN = (wid & 3) * 32;
    const int M0 = blockIdx.y * 128, N0 = blockIdx.x * 128;

    const __nv_bfloat16* srcs[4] = {Ah, Al, Bh, Bl};
    const int bases[4] = {M0, M0, N0, N0};

    auto issue = [&](int c, int s) {
        const int k0 = c << 6;
        #pragma unroll
        for (int arr = 0; arr < 4; arr++) {
            char* dstb = sm + s * STAGEB + arr * TILEB;
            const __nv_bfloat16* srcb = srcs[arr] + (size_t)bases[arr] * K + k0;
            #pragma unroll
            for (int i = 0; i < 4; i++) {
                int cc = i * 256 + tid;
                int r = cc >> 3, j = cc & 7;
                cpasync16(smem_u32(dstb + r * SROWB + j * 16),
                          srcb + (size_t)r * K + j * 8);
            }
        }
    };

    float acc[4][4][4];
    #pragma unroll
    for (int i = 0; i < 4; i++)
        #pragma unroll
        for (int j = 0; j < 4; j++)
            #pragma unroll
            for (int r = 0; r < 4; r++) acc[i][j][r] = 0.f;

    const int nch = K >> 6;
    issue(0, 0); cp_commit();

    for (int c = 0; c < nch; ++c) {
        if (c + 1 < nch) { issue(c + 1, (c + 1) & 1); cp_commit(); cp_wait1(); }
        else cp_wait0();
        __syncthreads();

        const char* base = sm + (c & 1) * STAGEB;
        #pragma unroll
        for (int ks = 0; ks < 4; ks++) {
            const int kb = ks * 16;
            uint32_t ah[4][4], al[4][4];
            #pragma unroll
            for (int fm = 0; fm < 4; fm++) {
                const char* rp = base + (warpM + fm * 16 + g) * SROWB + (kb + 2 * t) * 2;
                ah[fm][0] = *(const uint32_t*)(rp);
                ah[fm][1] = *(const uint32_t*)(rp + 8 * SROWB);
                ah[fm][2] = *(const uint32_t*)(rp + 16);
                ah[fm][3] = *(const uint32_t*)(rp + 8 * SROWB + 16);
                const char* rq = rp + TILEB;
                al[fm][0] = *(const uint32_t*)(rq);
                al[fm][1] = *(const uint32_t*)(rq + 8 * SROWB);
                al[fm][2] = *(const uint32_t*)(rq + 16);
                al[fm][3] = *(const uint32_t*)(rq + 8 * SROWB + 16);
            }
            uint32_t bh[4][2], bl[4][2];
            #pragma unroll
            for (int fn = 0; fn < 4; fn++) {
                const char* rp = base + 2 * TILEB + (warpN + fn * 8 + g) * SROWB + (kb + 2 * t) * 2;
                bh[fn][0] = *(const uint32_t*)(rp);
                bh[fn][1] = *(const uint32_t*)(rp + 16);
                bl[fn][0] = *(const uint32_t*)(rp + TILEB);
                bl[fn][1] = *(const uint32_t*)(rp + TILEB + 16);
            }
            #pragma unroll
            for (int fm = 0; fm < 4; fm++)
                #pragma unroll
                for (int fn = 0; fn < 4; fn++) {
                    mma_bf16(acc[fm][fn], ah[fm], bh[fn]);
                    mma_bf16(acc[fm][fn], ah[fm], bl[fn]);
                    mma_bf16(acc[fm][fn], al[fm], bh[fn]);
                }
        }
        __syncthreads();
    }

    #pragma unroll
    for (int fm = 0; fm < 4; fm++) {
        const int rbase = M0 + warpM + fm * 16 + g;
        #pragma unroll
        for (int half = 0; half < 2; half++) {
            const int row = rbase + half * 8;
            #pragma unroll
            for (int fn = 0; fn < 4; fn++) {
                const int col = N0 + warpN + fn * 8 + 2 * t;
                float v0 = acc[fm][fn][half * 2 + 0] + __ldg(&bias[col]);
                float v1 = acc[fm][fn][half * 2 + 1] + __ldg(&bias[col + 1]);
                if (RES) {
                    float2 rv = *(const float2*)(res + (size_t)row * N + col);
                    v0 += rv.x; v1 += rv.y;
                }
                if (RELU) { v0 = fmaxf(v0, 0.f); v1 = fmaxf(v1, 0.f); }
                if (SPLITOUT) {
                    __nv_bfloat16 h0,h1,l0,l1;
                    split_bf16(v0, h0, l0);
                    split_bf16(v1, h1, l1);
                    *(__nv_bfloat162*)(Ch + (size_t)row * N + col) = __nv_bfloat162{h0, h1};
                    *(__nv_bfloat162*)(Cl + (size_t)row * N + col) = __nv_bfloat162{l0, l1};
                } else {
                    *(float2*)(C + (size_t)row * N + col) = make_float2(v0, v1);
                }
            }
        }
    }
}

// ---------------------------------------------------------------- tensor-core flash attention
// grid (T/64, H, B), 128 thr (4 warps x m16 q-rows). BQ=64, BK=64, hd=64.
// qkv in split bf16 (hi/lo). Output ctx split bf16 into ch/cl.
#define KSTR 72   // smem row stride (bf16 elems): 144B, 16B-aligned, frag-conflict-free

__global__ __launch_bounds__(128)
void attn_mma_kernel(const __nv_bfloat16* __restrict__ qh_g, const __nv_bfloat16* __restrict__ ql_g,
                     const float* __restrict__ amask,
                     __nv_bfloat16* __restrict__ ch, __nv_bfloat16* __restrict__ cl) {
    const int q0 = blockIdx.x * 64;
    const int h = blockIdx.y, b = blockIdx.z;
    const int tid = threadIdx.x, lane = tid & 31, w = tid >> 5;
    const int g = lane >> 2, t = lane & 3;

    __shared__ alignas(16) __nv_bfloat16 Kh[64][KSTR], Kl[64][KSTR];
    __shared__ alignas(16) __nv_bfloat16 Vh[64][KSTR], Vl[64][KSTR];
    __shared__ float madd[64];

    // ---- Q fragments (once per block), rows w*16+g / +8 ----
    uint32_t qfh[4][4], qfl[4][4];
    {
        const size_t r0 = ((size_t)(b * TT + q0 + w * 16 + g)) * (3 * DD) + h * 64;
        const size_t r1 = r0 + (size_t)8 * (3 * DD);
        #pragma unroll
        for (int ks = 0; ks < 4; ks++) {
            int c = ks * 16 + 2 * t;
            qfh[ks][0] = *(const uint32_t*)(qh_g + r0 + c);
            qfh[ks][1] = *(const uint32_t*)(qh_g + r1 + c);
            qfh[ks][2] = *(const uint32_t*)(qh_g + r0 + c + 8);
            qfh[ks][3] = *(const uint32_t*)(qh_g + r1 + c + 8);
            qfl[ks][0] = *(const uint32_t*)(ql_g + r0 + c);
            qfl[ks][1] = *(const uint32_t*)(ql_g + r1 + c);
            qfl[ks][2] = *(const uint32_t*)(ql_g + r0 + c + 8);
            qfl[ks][3] = *(const uint32_t*)(ql_g + r1 + c + 8);
        }
    }

    float o[8][4];
    #pragma unroll
    for (int i = 0; i < 8; i++)
        #pragma unroll
        for (int j = 0; j < 4; j++) o[i][j] = 0.f;
    float m0 = -1e30f, m1 = -1e30f, l0 = 0.f, l1 = 0.f;

    for (int k0 = 0; k0 <= q0; k0 += 64) {
        // ---- load K, V tiles (split) via cp.async ----
        {
            const size_t gk = ((size_t)(b * TT + k0)) * (3 * DD) + DD + h * 64;
            const size_t gv = gk + DD;
            #pragma unroll
            for (int i = 0; i < 4; i++) {
                int cc = i * 128 + tid;
                int r = cc >> 3, j8 = (cc & 7) * 8;
                size_t rowoff = (size_t)r * (3 * DD) + j8;
                cpasync16(smem_u32(&Kh[r][j8]), qh_g + gk + rowoff);
                cpasync16(smem_u32(&Kl[r][j8]), ql_g + gk + rowoff);
                cpasync16(smem_u32(&Vh[r][j8]), qh_g + gv + rowoff);
                cpasync16(smem_u32(&Vl[r][j8]), ql_g + gv + rowoff);
            }
            cp_commit();
        }
        if (tid < 64) madd[tid] = (1.0f - __ldg(&amask[b * TT + k0 + tid])) * MASK_BIAS;
        cp_wait0();
        __syncthreads();

        // ---- S = Q K^T (bf16 x3) ----
        float s[8][4];
        #pragma unroll
        for (int i = 0; i < 8; i++)
            #pragma unroll
            for (int j = 0; j < 4; j++) s[i][j] = 0.f;
        #pragma unroll
        for (int ks = 0; ks < 4; ks++) {
            const int kb = ks * 16 + 2 * t;
            #pragma unroll
            for (int nt = 0; nt < 8; nt++) {
                uint32_t bh[2], bl[2];
                const __nv_bfloat16* rp = &Kh[nt * 8 + g][kb];
                bh[0] = *(const uint32_t*)(rp);
                bh[1] = *(const uint32_t*)(rp + 8);
                const __nv_bfloat16* rq = &Kl[nt * 8 + g][kb];
                bl[0] = *(const uint32_t*)(rq);
                bl[1] = *(const uint32_t*)(rq + 8);
                mma_bf16(s[nt], qfh[ks], bh);
                mma_bf16(s[nt], qfh[ks], bl);
                mma_bf16(s[nt], qfl[ks], bh);
            }
        }

        // ---- scale + masks ----
        const int r0g = q0 + w * 16 + g, r1g = r0g + 8;
        const bool diag = (k0 == q0);
        #pragma unroll
        for (int nt = 0; nt < 8; nt++) {
            int c0 = nt * 8 + 2 * t, c1 = c0 + 1;
            float ma0 = madd[c0], ma1 = madd[c1];
            int gc0 = k0 + c0, gc1 = k0 + c1;
            float v;
            v = s[nt][0] * 0.125f; if (diag && gc0 > r0g) v = MASK_BIAS; s[nt][0] = v + ma0;
            v = s[nt][1] * 0.125f; if (diag && gc1 > r0g) v = MASK_BIAS; s[nt][1] = v + ma1;
            v = s[nt][2] * 0.125f; if (diag && gc0 > r1g) v = MASK_BIAS; s[nt][2] = v + ma0;
            v = s[nt][3] * 0.125f; if (diag && gc1 > r1g) v = MASK_BIAS; s[nt][3] = v + ma1;
        }

        // ---- online softmax (rows g, g+8; reduce over 4 lanes of quad) ----
        float rx0 = -1e30f, rx1 = -1e30f;
        #pragma unroll
        for (int nt = 0; nt < 8; nt++) {
            rx0 = fmaxf(rx0, fmaxf(s[nt][0], s[nt][1]));
            rx1 = fmaxf(rx1, fmaxf(s[nt][2], s[nt][3]));
        }
        rx0 = fmaxf(rx0, __shfl_xor_sync(0xffffffffu, rx0, 1));
        rx0 = fmaxf(rx0, __shfl_xor_sync(0xffffffffu, rx0, 2));
        rx1 = fmaxf(rx1, __shfl_xor_sync(0xffffffffu, rx1, 1));
        rx1 = fmaxf(rx1, __shfl_xor_sync(0xffffffffu, rx1, 2));
        float m0n = fmaxf(m0, rx0), m1n = fmaxf(m1, rx1);
        float a0 = __expf(m0 - m0n), a1 = __expf(m1 - m1n);
        float sum0 = 0.f, sum1 = 0.f;
        #pragma unroll
        for (int nt = 0; nt < 8; nt++) {
            s[nt][0] = __expf(s[nt][0] - m0n);
            s[nt][1] = __expf(s[nt][1] - m0n);
            s[nt][2] = __expf(s[nt][2] - m1n);
            s[nt][3] = __expf(s[nt][3] - m1n);
            sum0 += s[nt][0] + s[nt][1];
            sum1 += s[nt][2] + s[nt][3];
        }
        sum0 += __shfl_xor_sync(0xffffffffu, sum0, 1);
        sum0 += __shfl_xor_sync(0xffffffffu, sum0, 2);
        sum1 += __shfl_xor_sync(0xffffffffu, sum1, 1);
        sum1 += __shfl_xor_sync(0xffffffffu, sum1, 2);
        l0 = l0 * a0 + sum0; l1 = l1 * a1 + sum1;
        m0 = m0n; m1 = m1n;
        #pragma unroll
        for (int nt = 0; nt < 8; nt++) {
            o[nt][0] *= a0; o[nt][1] *= a0;
            o[nt][2] *= a1; o[nt][3] *= a1;
        }

        // ---- P fragments (split hi/lo) ----
        uint32_t ph[4][4], pl[4][4];
        #pragma unroll
        for (int j = 0; j < 4; j++) {
            float* pa = s[2 * j];
            float* pb = s[2 * j + 1];
            ph[j][0] = pack_bf16(pa[0], pa[1]);
            ph[j][1] = pack_bf16(pa[2], pa[3]);
            ph[j][2] = pack_bf16(pb[0], pb[1]);
            ph[j][3] = pack_bf16(pb[2], pb[3]);
            __nv_bfloat162 h0 = *(__nv_bfloat162*)&ph[j][0];
            __nv_bfloat162 h1 = *(__nv_bfloat162*)&ph[j][1];
            __nv_bfloat162 h2 = *(__nv_bfloat162*)&ph[j][2];
            __nv_bfloat162 h3 = *(__nv_bfloat162*)&ph[j][3];
            pl[j][0] = pack_bf16(pa[0] - __bfloat162float(h0.x), pa[1] - __bfloat162float(h0.y));
            pl[j][1] = pack_bf16(pa[2] - __bfloat162float(h1.x), pa[3] - __bfloat162float(h1.y));
            pl[j][2] = pack_bf16(pb[0] - __bfloat162float(h2.x), pb[1] - __bfloat162float(h2.y));
            pl[j][3] = pack_bf16(pb[2] - __bfloat162float(h3.x), pb[3] - __bfloat162float(h3.y));
        }

        // ---- O += P V (bf16 x3), V frags via ldmatrix.trans ----
        #pragma unroll
        for (int ks = 0; ks < 4; ks++) {
            // b-frags for 8 d-tiles: 4 x ldmatrix.x4 (2 tiles each) per array
            uint32_t vh[8][2], vl[8][2];
            #pragma unroll
            for (int p2 = 0; p2 < 4; p2++) {
                // tiles: (khalf = lane>>3 & 1, ntile offset = lane>>4)
                int tile = lane >> 3, rown = lane & 7;
                int row = ks * 16 + (tile & 1) * 8 + rown;
                int col = (p2 * 2 + (tile >> 1)) * 8;
                uint32_t r4[4];
                ldmx4_trans(r4, smem_u32(&Vh[row][col]));
                vh[p2 * 2][0] = r4[0]; vh[p2 * 2][1] = r4[1];
                vh[p2 * 2 + 1][0] = r4[2]; vh[p2 * 2 + 1][1] = r4[3];
                ldmx4_trans(r4, smem_u32(&Vl[row][col]));
                vl[p2 * 2][0] = r4[0]; vl[p2 * 2][1] = r4[1];
                vl[p2 * 2 + 1][0] = r4[2]; vl[p2 * 2 + 1][1] = r4[3];
            }
            #pragma unroll
            for (int nt = 0; nt < 8; nt++) {
                mma_bf16(o[nt], ph[ks], vh[nt]);
                mma_bf16(o[nt], ph[ks], vl[nt]);
                mma_bf16(o[nt], pl[ks], vh[nt]);
            }
        }
        __syncthreads();
    }

    // ---- normalize + split-write ctx ----
    float inv0 = 1.f / l0, inv1 = 1.f / l1;
    const size_t ro0 = (size_t)(b * TT + q0 + w * 16 + g) * DD + h * 64;
    const size_t ro1 = ro0 + (size_t)8 * DD;
    #pragma unroll
    for (int nt = 0; nt < 8; nt++) {
        int c = nt * 8 + 2 * t;
        float v0 = o[nt][0] * inv0, v1 = o[nt][1] * inv0;
        float v2 = o[nt][2] * inv1, v3 = o[nt][3] * inv1;
        __nv_bfloat16 h0,h1,h2,h3,l0b,l1b,l2b,l3b;
        split_bf16(v0,h0,l0b); split_bf16(v1,h1,l1b);
        split_bf16(v2,h2,l2b); split_bf16(v3,h3,l3b);
        *(__nv_bfloat162*)(ch + ro0 + c) = __nv_bfloat162{h0, h1};
        *(__nv_bfloat162*)(cl + ro0 + c) = __nv_bfloat162{l0b, l1b};
        *(__nv_bfloat162*)(ch + ro1 + c) = __nv_bfloat162{h2, h3};
        *(__nv_bfloat162*)(cl + ro1 + c) = __nv_bfloat162{l2b, l3b};
    }
}

// ---------------------------------------------------------------- launch
extern "C" void kernel_launch(void* const* d_in, const int* in_sizes, int n_in,
                              void* d_out, int out_size) {
    const float* emb   = (const float*)d_in[0];
    const float* amask = (const float*)d_in[1];
    const float* ln1w  = (const float*)d_in[2];
    const float* ln1b  = (const float*)d_in[3];
    const float* attnw = (const float*)d_in[4];
    const float* attnb = (const float*)d_in[5];
    const float* projw = (const float*)d_in[6];
    const float* projb = (const float*)d_in[7];
    const float* ln2w  = (const float*)d_in[8];
    const float* ln2b  = (const float*)d_in[9];
    const float* fcw   = (const float*)d_in[10];
    const float* fcb   = (const float*)d_in[11];
    const float* fcpw  = (const float*)d_in[12];
    const float* fcpb  = (const float*)d_in[13];
    const float* lnfw  = (const float*)d_in[14];
    const float* lnfb  = (const float*)d_in[15];
    float* out = (float*)d_out;

    float *H;
    __nv_bfloat16 *Ah, *Al, *Fh, *Fl, *Wh, *Wl;
    cudaGetSymbolAddress((void**)&H,   g_H);
    cudaGetSymbolAddress((void**)&Ah,  g_Ah);
    cudaGetSymbolAddress((void**)&Al,  g_Al);
    cudaGetSymbolAddress((void**)&Fh,  g_Fh);
    cudaGetSymbolAddress((void**)&Fl,  g_Fl);
    cudaGetSymbolAddress((void**)&Wh,  g_Wh);
    cudaGetSymbolAddress((void**)&Wl,  g_Wl);

    cudaFuncSetAttribute(gemm_mma<false,false,true >, cudaFuncAttributeMaxDynamicSharedMemorySize, GSMEM);
    cudaFuncSetAttribute(gemm_mma<true, false,false>, cudaFuncAttributeMaxDynamicSharedMemorySize, GSMEM);
    cudaFuncSetAttribute(gemm_mma<false,true, true >, cudaFuncAttributeMaxDynamicSharedMemorySize, GSMEM);

    const int n4 = (MROWS * DD) / 4;
    copy_kernel<<<(n4 + 255) / 256, 256>>>((const float4*)emb, (float4*)H, n4);

    for (int l = 0; l < LL; l++) {
        const size_t wq = (size_t)l * DD * 3 * DD;
        const size_t wp = (size_t)l * DD * DD;
        const size_t wf = (size_t)l * DD * II;
        const size_t wg = (size_t)l * II * DD;

        // --- attention ---
        ln_split_kernel<<<MROWS, 256>>>(H, ln1w + l * DD, ln1b + l * DD, Ah, Al);
        splitT_kernel<<<dim3(3 * DD / 32, DD / 32), 256>>>(attnw + wq, Wh, Wl, DD, 3 * DD);
        gemm_mma<false,false,true><<<dim3(3 * DD / 128, MROWS / 128), 256, GSMEM>>>(
            Ah, Al, Wh, Wl, attnb + (size_t)l * 3 * DD, nullptr, nullptr, Fh, Fl, 3 * DD, DD);
        attn_mma_kernel<<<dim3(TT / 64, HH, BB), 128>>>(Fh, Fl, amask, Ah, Al);
        splitT_kernel<<<dim3(DD / 32, DD / 32), 256>>>(projw + wp, Wh, Wl, DD, DD);
        gemm_mma<true,false,false><<<dim3(DD / 128, MROWS / 128), 256, GSMEM>>>(
            Ah, Al, Wh, Wl, projb + (size_t)l * DD, H, H, nullptr, nullptr, DD, DD);

        // --- feed-forward ---
        ln_split_kernel<<<MROWS, 256>>>(H, ln2w + l * DD, ln2b + l * DD, Ah, Al);
        splitT_kernel<<<dim3(II / 32, DD / 32), 256>>>(fcw + wf, Wh, Wl, DD, II);
        gemm_mma<false,true,true><<<dim3(II / 128, MROWS / 128), 256, GSMEM>>>(
            Ah, Al, Wh, Wl, fcb + (size_t)l * II, nullptr, nullptr, Fh, Fl, II, DD);
        splitT_kernel<<<dim3(DD / 32, II / 32), 256>>>(fcpw + wg, Wh, Wl, II, DD);
        gemm_mma<true,false,false><<<dim3(DD / 128, MROWS / 128), 256, GSMEM>>>(
            Fh, Fl, Wh, Wl, fcpb + (size_t)l * DD, H, H, nullptr, nullptr, DD, II);
    }
    ln_kernel<<<MROWS, 256>>>(H, lnfw, lnfb, out);
}

// round 10
// speedup vs baseline: 1.5554x; 1.5554x over previous
#include <cuda_runtime.h>
#include <cuda_bf16.h>
#include <math.h>
#include <stdint.h>

#define BB 2
#define TT 2048
#define DD 1024
#define HH 16
#define LL 8
#define II 4096
#define MROWS (BB*TT)          // 4096
#define MASK_BIAS (-10000.0f)

// -------- scratch (no allocations allowed) --------
static __device__ float g_H  [(size_t)MROWS*DD];          // residual stream (f32)
static __device__ __nv_bfloat16 g_Ah[(size_t)MROWS*II];   // activation split hi (X / CTX)
static __device__ __nv_bfloat16 g_Al[(size_t)MROWS*II];   // activation split lo
static __device__ __nv_bfloat16 g_Fh[(size_t)MROWS*II];   // FF / QKV split hi
static __device__ __nv_bfloat16 g_Fl[(size_t)MROWS*II];   // FF / QKV split lo
static __device__ __nv_bfloat16 g_Wh[(size_t)II*DD];      // weight^T split hi [N x K]
static __device__ __nv_bfloat16 g_Wl[(size_t)II*DD];      // weight^T split lo

// ---------------------------------------------------------------- helpers
__device__ __forceinline__ uint32_t smem_u32(const void* p) {
    return (uint32_t)__cvta_generic_to_shared(p);
}

__device__ __forceinline__ void split_bf16(float x, __nv_bfloat16& h, __nv_bfloat16& l) {
    h = __float2bfloat16(x);
    l = __float2bfloat16(x - __bfloat162float(h));
}

__device__ __forceinline__ void mma_bf16(float* c, const uint32_t* a, const uint32_t* b) {
    asm volatile(
        "mma.sync.aligned.m16n8k16.row.col.f32.bf16.bf16.f32 "
        "{%0,%1,%2,%3},{%4,%5,%6,%7},{%8,%9},{%0,%1,%2,%3};"
        : "+f"(c[0]), "+f"(c[1]), "+f"(c[2]), "+f"(c[3])
        : "r"(a[0]), "r"(a[1]), "r"(a[2]), "r"(a[3]), "r"(b[0]), "r"(b[1]));
}

__device__ __forceinline__ void cpasync16(uint32_t dst, const void* src) {
    asm volatile("cp.async.cg.shared.global [%0], [%1], 16;" :: "r"(dst), "l"(src));
}
__device__ __forceinline__ void cp_commit() { asm volatile("cp.async.commit_group;"); }
__device__ __forceinline__ void cp_wait1()  { asm volatile("cp.async.wait_group 1;"); }
__device__ __forceinline__ void cp_wait0()  { asm volatile("cp.async.wait_group 0;"); }

__device__ __forceinline__ void ldmx4_trans(uint32_t* r, uint32_t saddr) {
    asm volatile("ldmatrix.sync.aligned.m8n8.x4.trans.shared.b16 {%0,%1,%2,%3}, [%4];"
        : "=r"(r[0]), "=r"(r[1]), "=r"(r[2]), "=r"(r[3]) : "r"(saddr));
}

__device__ __forceinline__ uint32_t pack_bf16(float x, float y) {
    __nv_bfloat162 v = __float22bfloat162_rn(float2{x, y});
    return *(uint32_t*)&v;
}

// ---------------------------------------------------------------- copy
__global__ void copy_kernel(const float4* __restrict__ src, float4* __restrict__ dst, int n4) {
    int i = blockIdx.x * blockDim.x + threadIdx.x;
    if (i < n4) dst[i] = src[i];
}

// ---------------------------------------------------------------- layernorm core (256 thr, D=1024)
__device__ __forceinline__ float4 ln_core(const float* __restrict__ in,
                                          const float* __restrict__ w,
                                          const float* __restrict__ bsc, int row, int t) {
    const float4* x4 = (const float4*)(in + (size_t)row * DD);
    float4 v = x4[t];
    float s = v.x + v.y + v.z + v.w;
    float q = v.x*v.x + v.y*v.y + v.z*v.z + v.w*v.w;
    #pragma unroll
    for (int o = 16; o; o >>= 1) {
        s += __shfl_xor_sync(0xffffffffu, s, o);
        q += __shfl_xor_sync(0xffffffffu, q, o);
    }
    __shared__ float ss[8], sq[8];
    __shared__ float red[2];
    int wid = t >> 5, lane = t & 31;
    if (lane == 0) { ss[wid] = s; sq[wid] = q; }
    __syncthreads();
    if (t == 0) {
        float S = 0.f, Q = 0.f;
        #pragma unroll
        for (int i = 0; i < 8; i++) { S += ss[i]; Q += sq[i]; }
        float mean = S * (1.0f / DD);
        float var  = Q * (1.0f / DD) - mean * mean;
        red[0] = mean;
        red[1] = rsqrtf(var + 1e-5f);
    }
    __syncthreads();
    float mean = red[0], inv = red[1];
    float4 wv = ((const float4*)w)[t];
    float4 bv = ((const float4*)bsc)[t];
    float4 o;
    o.x = (v.x - mean) * inv * wv.x + bv.x;
    o.y = (v.y - mean) * inv * wv.y + bv.y;
    o.z = (v.z - mean) * inv * wv.z + bv.z;
    o.w = (v.w - mean) * inv * wv.w + bv.w;
    return o;
}

__global__ void ln_kernel(const float* __restrict__ in, const float* __restrict__ w,
                          const float* __restrict__ bsc, float* __restrict__ out) {
    int row = blockIdx.x, t = threadIdx.x;
    float4 o = ln_core(in, w, bsc, row, t);
    ((float4*)(out + (size_t)row * DD))[t] = o;
}

__global__ void ln_split_kernel(const float* __restrict__ in, const float* __restrict__ w,
                                const float* __restrict__ bsc,
                                __nv_bfloat16* __restrict__ oh, __nv_bfloat16* __restrict__ ol) {
    int row = blockIdx.x, t = threadIdx.x;
    float4 o = ln_core(in, w, bsc, row, t);
    __nv_bfloat16 h0,h1,h2,h3,l0,l1,l2,l3;
    split_bf16(o.x,h0,l0); split_bf16(o.y,h1,l1); split_bf16(o.z,h2,l2); split_bf16(o.w,h3,l3);
    size_t idx = (size_t)row * DD + t * 4;
    *(__nv_bfloat162*)(oh + idx)     = __nv_bfloat162{h0,h1};
    *(__nv_bfloat162*)(oh + idx + 2) = __nv_bfloat162{h2,h3};
    *(__nv_bfloat162*)(ol + idx)     = __nv_bfloat162{l0,l1};
    *(__nv_bfloat162*)(ol + idx + 2) = __nv_bfloat162{l2,l3};
}

// ---------------------------------------------------------------- weight transpose + split
// W: [K x N] f32 row-major  ->  Th/Tl: [N x K] bf16
__global__ void splitT_kernel(const float* __restrict__ W, __nv_bfloat16* __restrict__ Th,
                              __nv_bfloat16* __restrict__ Tl, int K, int N) {
    __shared__ float t[32][33];
    int k0 = blockIdx.y * 32, n0 = blockIdx.x * 32;
    int tx = threadIdx.x & 31, ty = threadIdx.x >> 5;   // 8 rows per pass
    #pragma unroll
    for (int i = 0; i < 4; i++) {
        int r = ty + i * 8;
        t[r][tx] = W[(size_t)(k0 + r) * N + n0 + tx];
    }
    __syncthreads();
    #pragma unroll
    for (int i = 0; i < 4; i++) {
        int r = ty + i * 8;
        float v = t[tx][r];                 // = W[k0+tx][n0+r]
        __nv_bfloat16 h, l;
        split_bf16(v, h, l);
        size_t o = (size_t)(n0 + r) * K + k0 + tx;
        Th[o] = h; Tl[o] = l;
    }
}

// ---------------------------------------------------------------- bf16x3 mma.sync GEMM
// C[m][n] = sum_k A[m][k]*W[k][n] + bias (+res)(+relu). B operand = W^T [N x K] bf16.
// CTA 128x128, BK=64, 8 warps (2x4), warp tile 64x32, double-buffered cp.async.
// 3-term compensation issued in 3 PASSES so consecutive MMAs hit different accumulators.
#define SROWB   144                       // bytes per smem row (64 bf16 + 8 pad)
#define TILEB   (128 * SROWB)             // 18432 B
#define STAGEB  (4 * TILEB)               // Ah, Al, Bh, Bl
#define GSMEM   (2 * STAGEB)              // 147456 B

template<bool RES, bool RELU, bool SPLITOUT>
__global__ __launch_bounds__(256)
void gemm_mma(const __nv_bfloat16* __restrict__ Ah, const __nv_bfloat16* __restrict__ Al,
              const __nv_bfloat16* __restrict__ Bh, const __nv_bfloat16* __restrict__ Bl,
              const float* __restrict__ bias, const float* __restrict__ res,
              float* __restrict__ C, __nv_bfloat16* __restrict__ Ch, __nv_bfloat16* __restrict__ Cl,
              int N, int K) {
    extern __shared__ char sm[];
    const int tid = threadIdx.x, lane = tid & 31, wid = tid >> 5;
    const int g = lane >> 2, t = lane & 3;
    const int warpM = (wid >> 2) * 64, warpN = (wid & 3) * 32;
    const int M0 = blockIdx.y * 128, N0 = blockIdx.x * 128;

    const __nv_bfloat16* srcs[4] = {Ah, Al, Bh, Bl};
    const int bases[4] = {M0, M0, N0, N0};

    auto issue = [&](int c, int s) {
        const int k0 = c << 6;
        #pragma unroll
        for (int arr = 0; arr < 4; arr++) {
            char* dstb = sm + s * STAGEB + arr * TILEB;
            const __nv_bfloat16* srcb = srcs[arr] + (size_t)bases[arr] * K + k0;
            #pragma unroll
            for (int i = 0; i < 4; i++) {
                int cc = i * 256 + tid;
                int r = cc >> 3, j = cc & 7;
                cpasync16(smem_u32(dstb + r * SROWB + j * 16),
                          srcb + (size_t)r * K + j * 8);
            }
        }
    };

    float acc[4][4][4];
    #pragma unroll
    for (int i = 0; i < 4; i++)
        #pragma unroll
        for (int j = 0; j < 4; j++)
            #pragma unroll
            for (int r = 0; r < 4; r++) acc[i][j][r] = 0.f;

    const int nch = K >> 6;
    issue(0, 0); cp_commit();

    for (int c = 0; c < nch; ++c) {
        if (c + 1 < nch) { issue(c + 1, (c + 1) & 1); cp_commit(); cp_wait1(); }
        else cp_wait0();
        __syncthreads();

        const char* base = sm + (c & 1) * STAGEB;
        #pragma unroll
        for (int ks = 0; ks < 4; ks++) {
            const int kb = ks * 16;
            uint32_t ah[4][4], al[4][4];
            #pragma unroll
            for (int fm = 0; fm < 4; fm++) {
                const char* rp = base + (warpM + fm * 16 + g) * SROWB + (kb + 2 * t) * 2;
                ah[fm][0] = *(const uint32_t*)(rp);
                ah[fm][1] = *(const uint32_t*)(rp + 8 * SROWB);
                ah[fm][2] = *(const uint32_t*)(rp + 16);
                ah[fm][3] = *(const uint32_t*)(rp + 8 * SROWB + 16);
                const char* rq = rp + TILEB;
                al[fm][0] = *(const uint32_t*)(rq);
                al[fm][1] = *(const uint32_t*)(rq + 8 * SROWB);
                al[fm][2] = *(const uint32_t*)(rq + 16);
                al[fm][3] = *(const uint32_t*)(rq + 8 * SROWB + 16);
            }
            uint32_t bh[4][2], bl[4][2];
            #pragma unroll
            for (int fn = 0; fn < 4; fn++) {
                const char* rp = base + 2 * TILEB + (warpN + fn * 8 + g) * SROWB + (kb + 2 * t) * 2;
                bh[fn][0] = *(const uint32_t*)(rp);
                bh[fn][1] = *(const uint32_t*)(rp + 16);
                bl[fn][0] = *(const uint32_t*)(rp + TILEB);
                bl[fn][1] = *(const uint32_t*)(rp + TILEB + 16);
            }
            // pass 1: hi*hi  (16 independent accumulators back-to-back)
            #pragma unroll
            for (int fm = 0; fm < 4; fm++)
                #pragma unroll
                for (int fn = 0; fn < 4; fn++)
                    mma_bf16(acc[fm][fn], ah[fm], bh[fn]);
            // pass 2: hi*lo
            #pragma unroll
            for (int fm = 0; fm < 4; fm++)
                #pragma unroll
                for (int fn = 0; fn < 4; fn++)
                    mma_bf16(acc[fm][fn], ah[fm], bl[fn]);
            // pass 3: lo*hi
            #pragma unroll
            for (int fm = 0; fm < 4; fm++)
                #pragma unroll
                for (int fn = 0; fn < 4; fn++)
                    mma_bf16(acc[fm][fn], al[fm], bh[fn]);
        }
        __syncthreads();
    }

    #pragma unroll
    for (int fm = 0; fm < 4; fm++) {
        const int rbase = M0 + warpM + fm * 16 + g;
        #pragma unroll
        for (int half = 0; half < 2; half++) {
            const int row = rbase + half * 8;
            #pragma unroll
            for (int fn = 0; fn < 4; fn++) {
                const int col = N0 + warpN + fn * 8 + 2 * t;
                float v0 = acc[fm][fn][half * 2 + 0] + __ldg(&bias[col]);
                float v1 = acc[fm][fn][half * 2 + 1] + __ldg(&bias[col + 1]);
                if (RES) {
                    float2 rv = *(const float2*)(res + (size_t)row * N + col);
                    v0 += rv.x; v1 += rv.y;
                }
                if (RELU) { v0 = fmaxf(v0, 0.f); v1 = fmaxf(v1, 0.f); }
                if (SPLITOUT) {
                    __nv_bfloat16 h0,h1,l0,l1;
                    split_bf16(v0, h0, l0);
                    split_bf16(v1, h1, l1);
                    *(__nv_bfloat162*)(Ch + (size_t)row * N + col) = __nv_bfloat162{h0, h1};
                    *(__nv_bfloat162*)(Cl + (size_t)row * N + col) = __nv_bfloat162{l0, l1};
                } else {
                    *(float2*)(C + (size_t)row * N + col) = make_float2(v0, v1);
                }
            }
        }
    }
}

// ---------------------------------------------------------------- tensor-core flash attention
// grid (T/64, H, B), 128 thr (4 warps x m16 q-rows). BQ=64, BK=64, hd=64.
// qkv in split bf16 (hi/lo). Output ctx split bf16 into ch/cl.
#define KSTR 72   // smem row stride (bf16 elems): 144B, 16B-aligned, frag-conflict-free

__global__ __launch_bounds__(128)
void attn_mma_kernel(const __nv_bfloat16* __restrict__ qh_g, const __nv_bfloat16* __restrict__ ql_g,
                     const float* __restrict__ amask,
                     __nv_bfloat16* __restrict__ ch, __nv_bfloat16* __restrict__ cl) {
    const int q0 = blockIdx.x * 64;
    const int h = blockIdx.y, b = blockIdx.z;
    const int tid = threadIdx.x, lane = tid & 31, w = tid >> 5;
    const int g = lane >> 2, t = lane & 3;

    __shared__ alignas(16) __nv_bfloat16 Kh[64][KSTR], Kl[64][KSTR];
    __shared__ alignas(16) __nv_bfloat16 Vh[64][KSTR], Vl[64][KSTR];
    __shared__ float madd[64];

    // ---- Q fragments (once per block), rows w*16+g / +8 ----
    uint32_t qfh[4][4], qfl[4][4];
    {
        const size_t r0 = ((size_t)(b * TT + q0 + w * 16 + g)) * (3 * DD) + h * 64;
        const size_t r1 = r0 + (size_t)8 * (3 * DD);
        #pragma unroll
        for (int ks = 0; ks < 4; ks++) {
            int c = ks * 16 + 2 * t;
            qfh[ks][0] = *(const uint32_t*)(qh_g + r0 + c);
            qfh[ks][1] = *(const uint32_t*)(qh_g + r1 + c);
            qfh[ks][2] = *(const uint32_t*)(qh_g + r0 + c + 8);
            qfh[ks][3] = *(const uint32_t*)(qh_g + r1 + c + 8);
            qfl[ks][0] = *(const uint32_t*)(ql_g + r0 + c);
            qfl[ks][1] = *(const uint32_t*)(ql_g + r1 + c);
            qfl[ks][2] = *(const uint32_t*)(ql_g + r0 + c + 8);
            qfl[ks][3] = *(const uint32_t*)(ql_g + r1 + c + 8);
        }
    }

    float o[8][4];
    #pragma unroll
    for (int i = 0; i < 8; i++)
        #pragma unroll
        for (int j = 0; j < 4; j++) o[i][j] = 0.f;
    float m0 = -1e30f, m1 = -1e30f, l0 = 0.f, l1 = 0.f;

    for (int k0 = 0; k0 <= q0; k0 += 64) {
        // ---- load K, V tiles (split) via cp.async ----
        {
            const size_t gk = ((size_t)(b * TT + k0)) * (3 * DD) + DD + h * 64;
            const size_t gv = gk + DD;
            #pragma unroll
            for (int i = 0; i < 4; i++) {
                int cc = i * 128 + tid;
                int r = cc >> 3, j8 = (cc & 7) * 8;
                size_t rowoff = (size_t)r * (3 * DD) + j8;
                cpasync16(smem_u32(&Kh[r][j8]), qh_g + gk + rowoff);
                cpasync16(smem_u32(&Kl[r][j8]), ql_g + gk + rowoff);
                cpasync16(smem_u32(&Vh[r][j8]), qh_g + gv + rowoff);
                cpasync16(smem_u32(&Vl[r][j8]), ql_g + gv + rowoff);
            }
            cp_commit();
        }
        if (tid < 64) madd[tid] = (1.0f - __ldg(&amask[b * TT + k0 + tid])) * MASK_BIAS;
        cp_wait0();
        __syncthreads();

        // ---- S = Q K^T (bf16 x3, 3-pass ordering) ----
        float s[8][4];
        #pragma unroll
        for (int i = 0; i < 8; i++)
            #pragma unroll
            for (int j = 0; j < 4; j++) s[i][j] = 0.f;
        #pragma unroll
        for (int ks = 0; ks < 4; ks++) {
            const int kb = ks * 16 + 2 * t;
            uint32_t bh[8][2], bl[8][2];
            #pragma unroll
            for (int nt = 0; nt < 8; nt++) {
                const __nv_bfloat16* rp = &Kh[nt * 8 + g][kb];
                bh[nt][0] = *(const uint32_t*)(rp);
                bh[nt][1] = *(const uint32_t*)(rp + 8);
                const __nv_bfloat16* rq = &Kl[nt * 8 + g][kb];
                bl[nt][0] = *(const uint32_t*)(rq);
                bl[nt][1] = *(const uint32_t*)(rq + 8);
            }
            #pragma unroll
            for (int nt = 0; nt < 8; nt++) mma_bf16(s[nt], qfh[ks], bh[nt]);
            #pragma unroll
            for (int nt = 0; nt < 8; nt++) mma_bf16(s[nt], qfh[ks], bl[nt]);
            #pragma unroll
            for (int nt = 0; nt < 8; nt++) mma_bf16(s[nt], qfl[ks], bh[nt]);
        }

        // ---- scale + masks ----
        const int r0g = q0 + w * 16 + g, r1g = r0g + 8;
        const bool diag = (k0 == q0);
        #pragma unroll
        for (int nt = 0; nt < 8; nt++) {
            int c0 = nt * 8 + 2 * t, c1 = c0 + 1;
            float ma0 = madd[c0], ma1 = madd[c1];
            int gc0 = k0 + c0, gc1 = k0 + c1;
            float v;
            v = s[nt][0] * 0.125f; if (diag && gc0 > r0g) v = MASK_BIAS; s[nt][0] = v + ma0;
            v = s[nt][1] * 0.125f; if (diag && gc1 > r0g) v = MASK_BIAS; s[nt][1] = v + ma1;
            v = s[nt][2] * 0.125f; if (diag && gc0 > r1g) v = MASK_BIAS; s[nt][2] = v + ma0;
            v = s[nt][3] * 0.125f; if (diag && gc1 > r1g) v = MASK_BIAS; s[nt][3] = v + ma1;
        }

        // ---- online softmax (rows g, g+8; reduce over 4 lanes of quad) ----
        float rx0 = -1e30f, rx1 = -1e30f;
        #pragma unroll
        for (int nt = 0; nt < 8; nt++) {
            rx0 = fmaxf(rx0, fmaxf(s[nt][0], s[nt][1]));
            rx1 = fmaxf(rx1, fmaxf(s[nt][2], s[nt][3]));
        }
        rx0 = fmaxf(rx0, __shfl_xor_sync(0xffffffffu, rx0, 1));
        rx0 = fmaxf(rx0, __shfl_xor_sync(0xffffffffu, rx0, 2));
        rx1 = fmaxf(rx1, __shfl_xor_sync(0xffffffffu, rx1, 1));
        rx1 = fmaxf(rx1, __shfl_xor_sync(0xffffffffu, rx1, 2));
        float m0n = fmaxf(m0, rx0), m1n = fmaxf(m1, rx1);
        float a0 = __expf(m0 - m0n), a1 = __expf(m1 - m1n);
        float sum0 = 0.f, sum1 = 0.f;
        #pragma unroll
        for (int nt = 0; nt < 8; nt++) {
            s[nt][0] = __expf(s[nt][0] - m0n);
            s[nt][1] = __expf(s[nt][1] - m0n);
            s[nt][2] = __expf(s[nt][2] - m1n);
            s[nt][3] = __expf(s[nt][3] - m1n);
            sum0 += s[nt][0] + s[nt][1];
            sum1 += s[nt][2] + s[nt][3];
        }
        sum0 += __shfl_xor_sync(0xffffffffu, sum0, 1);
        sum0 += __shfl_xor_sync(0xffffffffu, sum0, 2);
        sum1 += __shfl_xor_sync(0xffffffffu, sum1, 1);
        sum1 += __shfl_xor_sync(0xffffffffu, sum1, 2);
        l0 = l0 * a0 + sum0; l1 = l1 * a1 + sum1;
        m0 = m0n; m1 = m1n;
        #pragma unroll
        for (int nt = 0; nt < 8; nt++) {
            o[nt][0] *= a0; o[nt][1] *= a0;
            o[nt][2] *= a1; o[nt][3] *= a1;
        }

        // ---- P fragments (split hi/lo) ----
        uint32_t ph[4][4], pl[4][4];
        #pragma unroll
        for (int j = 0; j < 4; j++) {
            float* pa = s[2 * j];
            float* pb = s[2 * j + 1];
            ph[j][0] = pack_bf16(pa[0], pa[1]);
            ph[j][1] = pack_bf16(pa[2], pa[3]);
            ph[j][2] = pack_bf16(pb[0], pb[1]);
            ph[j][3] = pack_bf16(pb[2], pb[3]);
            __nv_bfloat162 h0 = *(__nv_bfloat162*)&ph[j][0];
            __nv_bfloat162 h1 = *(__nv_bfloat162*)&ph[j][1];
            __nv_bfloat162 h2 = *(__nv_bfloat162*)&ph[j][2];
            __nv_bfloat162 h3 = *(__nv_bfloat162*)&ph[j][3];
            pl[j][0] = pack_bf16(pa[0] - __bfloat162float(h0.x), pa[1] - __bfloat162float(h0.y));
            pl[j][1] = pack_bf16(pa[2] - __bfloat162float(h1.x), pa[3] - __bfloat162float(h1.y));
            pl[j][2] = pack_bf16(pb[0] - __bfloat162float(h2.x), pb[1] - __bfloat162float(h2.y));
            pl[j][3] = pack_bf16(pb[2] - __bfloat162float(h3.x), pb[3] - __bfloat162float(h3.y));
        }

        // ---- O += P V (bf16 x3, 3-pass), V frags via ldmatrix.trans ----
        #pragma unroll
        for (int ks = 0; ks < 4; ks++) {
            uint32_t vh[8][2], vl[8][2];
            #pragma unroll
            for (int p2 = 0; p2 < 4; p2++) {
                int tile = lane >> 3, rown = lane & 7;
                int row = ks * 16 + (tile & 1) * 8 + rown;
                int col = (p2 * 2 + (tile >> 1)) * 8;
                uint32_t r4[4];
                ldmx4_trans(r4, smem_u32(&Vh[row][col]));
                vh[p2 * 2][0] = r4[0]; vh[p2 * 2][1] = r4[1];
                vh[p2 * 2 + 1][0] = r4[2]; vh[p2 * 2 + 1][1] = r4[3];
                ldmx4_trans(r4, smem_u32(&Vl[row][col]));
                vl[p2 * 2][0] = r4[0]; vl[p2 * 2][1] = r4[1];
                vl[p2 * 2 + 1][0] = r4[2]; vl[p2 * 2 + 1][1] = r4[3];
            }
            #pragma unroll
            for (int nt = 0; nt < 8; nt++) mma_bf16(o[nt], ph[ks], vh[nt]);
            #pragma unroll
            for (int nt = 0; nt < 8; nt++) mma_bf16(o[nt], ph[ks], vl[nt]);
            #pragma unroll
            for (int nt = 0; nt < 8; nt++) mma_bf16(o[nt], pl[ks], vh[nt]);
        }
        __syncthreads();
    }

    // ---- normalize + split-write ctx ----
    float inv0 = 1.f / l0, inv1 = 1.f / l1;
    const size_t ro0 = (size_t)(b * TT + q0 + w * 16 + g) * DD + h * 64;
    const size_t ro1 = ro0 + (size_t)8 * DD;
    #pragma unroll
    for (int nt = 0; nt < 8; nt++) {
        int c = nt * 8 + 2 * t;
        float v0 = o[nt][0] * inv0, v1 = o[nt][1] * inv0;
        float v2 = o[nt][2] * inv1, v3 = o[nt][3] * inv1;
        __nv_bfloat16 h0,h1,h2,h3,l0b,l1b,l2b,l3b;
        split_bf16(v0,h0,l0b); split_bf16(v1,h1,l1b);
        split_bf16(v2,h2,l2b); split_bf16(v3,h3,l3b);
        *(__nv_bfloat162*)(ch + ro0 + c) = __nv_bfloat162{h0, h1};
        *(__nv_bfloat162*)(cl + ro0 + c) = __nv_bfloat162{l0b, l1b};
        *(__nv_bfloat162*)(ch + ro1 + c) = __nv_bfloat162{h2, h3};
        *(__nv_bfloat162*)(cl + ro1 + c) = __nv_bfloat162{l2b, l3b};
    }
}

// ---------------------------------------------------------------- launch
extern "C" void kernel_launch(void* const* d_in, const int* in_sizes, int n_in,
                              void* d_out, int out_size) {
    const float* emb   = (const float*)d_in[0];
    const float* amask = (const float*)d_in[1];
    const float* ln1w  = (const float*)d_in[2];
    const float* ln1b  = (const float*)d_in[3];
    const float* attnw = (const float*)d_in[4];
    const float* attnb = (const float*)d_in[5];
    const float* projw = (const float*)d_in[6];
    const float* projb = (const float*)d_in[7];
    const float* ln2w  = (const float*)d_in[8];
    const float* ln2b  = (const float*)d_in[9];
    const float* fcw   = (const float*)d_in[10];
    const float* fcb   = (const float*)d_in[11];
    const float* fcpw  = (const float*)d_in[12];
    const float* fcpb  = (const float*)d_in[13];
    const float* lnfw  = (const float*)d_in[14];
    const float* lnfb  = (const float*)d_in[15];
    float* out = (float*)d_out;

    float *H;
    __nv_bfloat16 *Ah, *Al, *Fh, *Fl, *Wh, *Wl;
    cudaGetSymbolAddress((void**)&H,   g_H);
    cudaGetSymbolAddress((void**)&Ah,  g_Ah);
    cudaGetSymbolAddress((void**)&Al,  g_Al);
    cudaGetSymbolAddress((void**)&Fh,  g_Fh);
    cudaGetSymbolAddress((void**)&Fl,  g_Fl);
    cudaGetSymbolAddress((void**)&Wh,  g_Wh);
    cudaGetSymbolAddress((void**)&Wl,  g_Wl);

    cudaFuncSetAttribute(gemm_mma<false,false,true >, cudaFuncAttributeMaxDynamicSharedMemorySize, GSMEM);
    cudaFuncSetAttribute(gemm_mma<true, false,false>, cudaFuncAttributeMaxDynamicSharedMemorySize, GSMEM);
    cudaFuncSetAttribute(gemm_mma<false,true, true >, cudaFuncAttributeMaxDynamicSharedMemorySize, GSMEM);

    const int n4 = (MROWS * DD) / 4;
    copy_kernel<<<(n4 + 255) / 256, 256>>>((const float4*)emb, (float4*)H, n4);

    for (int l = 0; l < LL; l++) {
        const size_t wq = (size_t)l * DD * 3 * DD;
        const size_t wp = (size_t)l * DD * DD;
        const size_t wf = (size_t)l * DD * II;
        const size_t wg = (size_t)l * II * DD;

        // --- attention ---
        ln_split_kernel<<<MROWS, 256>>>(H, ln1w + l * DD, ln1b + l * DD, Ah, Al);
        splitT_kernel<<<dim3(3 * DD / 32, DD / 32), 256>>>(attnw + wq, Wh, Wl, DD, 3 * DD);
        gemm_mma<false,false,true><<<dim3(3 * DD / 128, MROWS / 128), 256, GSMEM>>>(
            Ah, Al, Wh, Wl, attnb + (size_t)l * 3 * DD, nullptr, nullptr, Fh, Fl, 3 * DD, DD);
        attn_mma_kernel<<<dim3(TT / 64, HH, BB), 128>>>(Fh, Fl, amask, Ah, Al);
        splitT_kernel<<<dim3(DD / 32, DD / 32), 256>>>(projw + wp, Wh, Wl, DD, DD);
        gemm_mma<true,false,false><<<dim3(DD / 128, MROWS / 128), 256, GSMEM>>>(
            Ah, Al, Wh, Wl, projb + (size_t)l * DD, H, H, nullptr, nullptr, DD, DD);

        // --- feed-forward ---
        ln_split_kernel<<<MROWS, 256>>>(H, ln2w + l * DD, ln2b + l * DD, Ah, Al);
        splitT_kernel<<<dim3(II / 32, DD / 32), 256>>>(fcw + wf, Wh, Wl, DD, II);
        gemm_mma<false,true,true><<<dim3(II / 128, MROWS / 128), 256, GSMEM>>>(
            Ah, Al, Wh, Wl, fcb + (size_t)l * II, nullptr, nullptr, Fh, Fl, II, DD);
        splitT_kernel<<<dim3(DD / 32, II / 32), 256>>>(fcpw + wg, Wh, Wl, II, DD);
        gemm_mma<true,false,false><<<dim3(DD / 128, MROWS / 128), 256, GSMEM>>>(
            Fh, Fl, Wh, Wl, fcpb + (size_t)l * DD, H, H, nullptr, nullptr, DD, II);
    }
    ln_kernel<<<MROWS, 256>>>(H, lnfw, lnfb, out);
}

// round 11
// speedup vs baseline: 1.5802x; 1.0160x over previous
#include <cuda_runtime.h>
#include <cuda_bf16.h>
#include <math.h>
#include <stdint.h>

#define BB 2
#define TT 2048
#define DD 1024
#define HH 16
#define LL 8
#define II 4096
#define MROWS (BB*TT)          // 4096
#define MASK_BIAS (-10000.0f)

// -------- scratch (no allocations allowed) --------
static __device__ float g_H  [(size_t)MROWS*DD];          // residual stream (f32)
static __device__ __nv_bfloat16 g_Ah[(size_t)MROWS*II];   // activation split hi (X / CTX)
static __device__ __nv_bfloat16 g_Al[(size_t)MROWS*II];   // activation split lo
static __device__ __nv_bfloat16 g_Fh[(size_t)MROWS*II];   // FF / QKV split hi
static __device__ __nv_bfloat16 g_Fl[(size_t)MROWS*II];   // FF / QKV split lo
static __device__ __nv_bfloat16 g_Wh[(size_t)II*DD];      // weight^T split hi [N x K]
static __device__ __nv_bfloat16 g_Wl[(size_t)II*DD];      // weight^T split lo

// ---------------------------------------------------------------- helpers
__device__ __forceinline__ uint32_t smem_u32(const void* p) {
    return (uint32_t)__cvta_generic_to_shared(p);
}

__device__ __forceinline__ void split_bf16(float x, __nv_bfloat16& h, __nv_bfloat16& l) {
    h = __float2bfloat16(x);
    l = __float2bfloat16(x - __bfloat162float(h));
}

__device__ __forceinline__ void mma_bf16(float* c, const uint32_t* a, const uint32_t* b) {
    asm volatile(
        "mma.sync.aligned.m16n8k16.row.col.f32.bf16.bf16.f32 "
        "{%0,%1,%2,%3},{%4,%5,%6,%7},{%8,%9},{%0,%1,%2,%3};"
        : "+f"(c[0]), "+f"(c[1]), "+f"(c[2]), "+f"(c[3])
        : "r"(a[0]), "r"(a[1]), "r"(a[2]), "r"(a[3]), "r"(b[0]), "r"(b[1]));
}

__device__ __forceinline__ void cpasync16(uint32_t dst, const void* src) {
    asm volatile("cp.async.cg.shared.global [%0], [%1], 16;" :: "r"(dst), "l"(src));
}
__device__ __forceinline__ void cp_commit() { asm volatile("cp.async.commit_group;"); }
__device__ __forceinline__ void cp_wait1()  { asm volatile("cp.async.wait_group 1;"); }
__device__ __forceinline__ void cp_wait0()  { asm volatile("cp.async.wait_group 0;"); }

__device__ __forceinline__ void ldmx4(uint32_t* r, uint32_t saddr) {
    asm volatile("ldmatrix.sync.aligned.m8n8.x4.shared.b16 {%0,%1,%2,%3}, [%4];"
        : "=r"(r[0]), "=r"(r[1]), "=r"(r[2]), "=r"(r[3]) : "r"(saddr));
}

__device__ __forceinline__ void ldmx4_trans(uint32_t* r, uint32_t saddr) {
    asm volatile("ldmatrix.sync.aligned.m8n8.x4.trans.shared.b16 {%0,%1,%2,%3}, [%4];"
        : "=r"(r[0]), "=r"(r[1]), "=r"(r[2]), "=r"(r[3]) : "r"(saddr));
}

__device__ __forceinline__ uint32_t pack_bf16(float x, float y) {
    __nv_bfloat162 v = __float22bfloat162_rn(float2{x, y});
    return *(uint32_t*)&v;
}

// ---------------------------------------------------------------- copy
__global__ void copy_kernel(const float4* __restrict__ src, float4* __restrict__ dst, int n4) {
    int i = blockIdx.x * blockDim.x + threadIdx.x;
    if (i < n4) dst[i] = src[i];
}

// ---------------------------------------------------------------- layernorm core (256 thr, D=1024)
__device__ __forceinline__ float4 ln_core(const float* __restrict__ in,
                                          const float* __restrict__ w,
                                          const float* __restrict__ bsc, int row, int t) {
    const float4* x4 = (const float4*)(in + (size_t)row * DD);
    float4 v = x4[t];
    float s = v.x + v.y + v.z + v.w;
    float q = v.x*v.x + v.y*v.y + v.z*v.z + v.w*v.w;
    #pragma unroll
    for (int o = 16; o; o >>= 1) {
        s += __shfl_xor_sync(0xffffffffu, s, o);
        q += __shfl_xor_sync(0xffffffffu, q, o);
    }
    __shared__ float ss[8], sq[8];
    __shared__ float red[2];
    int wid = t >> 5, lane = t & 31;
    if (lane == 0) { ss[wid] = s; sq[wid] = q; }
    __syncthreads();
    if (t == 0) {
        float S = 0.f, Q = 0.f;
        #pragma unroll
        for (int i = 0; i < 8; i++) { S += ss[i]; Q += sq[i]; }
        float mean = S * (1.0f / DD);
        float var  = Q * (1.0f / DD) - mean * mean;
        red[0] = mean;
        red[1] = rsqrtf(var + 1e-5f);
    }
    __syncthreads();
    float mean = red[0], inv = red[1];
    float4 wv = ((const float4*)w)[t];
    float4 bv = ((const float4*)bsc)[t];
    float4 o;
    o.x = (v.x - mean) * inv * wv.x + bv.x;
    o.y = (v.y - mean) * inv * wv.y + bv.y;
    o.z = (v.z - mean) * inv * wv.z + bv.z;
    o.w = (v.w - mean) * inv * wv.w + bv.w;
    return o;
}

__global__ void ln_kernel(const float* __restrict__ in, const float* __restrict__ w,
                          const float* __restrict__ bsc, float* __restrict__ out) {
    int row = blockIdx.x, t = threadIdx.x;
    float4 o = ln_core(in, w, bsc, row, t);
    ((float4*)(out + (size_t)row * DD))[t] = o;
}

__global__ void ln_split_kernel(const float* __restrict__ in, const float* __restrict__ w,
                                const float* __restrict__ bsc,
                                __nv_bfloat16* __restrict__ oh, __nv_bfloat16* __restrict__ ol) {
    int row = blockIdx.x, t = threadIdx.x;
    float4 o = ln_core(in, w, bsc, row, t);
    __nv_bfloat16 h0,h1,h2,h3,l0,l1,l2,l3;
    split_bf16(o.x,h0,l0); split_bf16(o.y,h1,l1); split_bf16(o.z,h2,l2); split_bf16(o.w,h3,l3);
    size_t idx = (size_t)row * DD + t * 4;
    *(__nv_bfloat162*)(oh + idx)     = __nv_bfloat162{h0,h1};
    *(__nv_bfloat162*)(oh + idx + 2) = __nv_bfloat162{h2,h3};
    *(__nv_bfloat162*)(ol + idx)     = __nv_bfloat162{l0,l1};
    *(__nv_bfloat162*)(ol + idx + 2) = __nv_bfloat162{l2,l3};
}

// ---------------------------------------------------------------- weight transpose + split
// W: [K x N] f32 row-major  ->  Th/Tl: [N x K] bf16
__global__ void splitT_kernel(const float* __restrict__ W, __nv_bfloat16* __restrict__ Th,
                              __nv_bfloat16* __restrict__ Tl, int K, int N) {
    __shared__ float t[32][33];
    int k0 = blockIdx.y * 32, n0 = blockIdx.x * 32;
    int tx = threadIdx.x & 31, ty = threadIdx.x >> 5;   // 8 rows per pass
    #pragma unroll
    for (int i = 0; i < 4; i++) {
        int r = ty + i * 8;
        t[r][tx] = W[(size_t)(k0 + r) * N + n0 + tx];
    }
    __syncthreads();
    #pragma unroll
    for (int i = 0; i < 4; i++) {
        int r = ty + i * 8;
        float v = t[tx][r];                 // = W[k0+tx][n0+r]
        __nv_bfloat16 h, l;
        split_bf16(v, h, l);
        size_t o = (size_t)(n0 + r) * K + k0 + tx;
        Th[o] = h; Tl[o] = l;
    }
}

// ---------------------------------------------------------------- bf16x3 mma.sync GEMM
// C[m][n] = sum_k A[m][k]*W[k][n] + bias (+res)(+relu). B operand = W^T [N x K] bf16.
// CTA 128x128, BK=64, 8 warps (2x4), warp tile 64x32.
// 3-stage cp.async pipeline, ONE sync per chunk, ldmatrix fragment loads,
// 3-pass compensation ordering.
#define SROWB   144                       // bytes per smem row (64 bf16 + 8 pad)
#define TILEB   (128 * SROWB)             // 18432 B
#define STAGEB  (4 * TILEB)               // Ah, Al, Bh, Bl
#define NSTAGE  3
#define GSMEM   (NSTAGE * STAGEB)         // 221184 B

template<bool RES, bool RELU, bool SPLITOUT>
__global__ __launch_bounds__(256)
void gemm_mma(const __nv_bfloat16* __restrict__ Ah, const __nv_bfloat16* __restrict__ Al,
              const __nv_bfloat16* __restrict__ Bh, const __nv_bfloat16* __restrict__ Bl,
              const float* __restrict__ bias, const float* __restrict__ res,
              float* __restrict__ C, __nv_bfloat16* __restrict__ Ch, __nv_bfloat16* __restrict__ Cl,
              int N, int K) {
    extern __shared__ char sm[];
    const int tid = threadIdx.x, lane = tid & 31, wid = tid >> 5;
    const int g = lane >> 2, t = lane & 3;
    const int warpM = (wid >> 2) * 64, warpN = (wid & 3) * 32;
    const int M0 = blockIdx.y * 128, N0 = blockIdx.x * 128;

    const __nv_bfloat16* srcs[4] = {Ah, Al, Bh, Bl};
    const int bases[4] = {M0, M0, N0, N0};

    auto issue = [&](int c, int s) {
        const int k0 = c << 6;
        #pragma unroll
        for (int arr = 0; arr < 4; arr++) {
            char* dstb = sm + s * STAGEB + arr * TILEB;
            const __nv_bfloat16* srcb = srcs[arr] + (size_t)bases[arr] * K + k0;
            #pragma unroll
            for (int i = 0; i < 4; i++) {
                int cc = i * 256 + tid;
                int r = cc >> 3, j = cc & 7;
                cpasync16(smem_u32(dstb + r * SROWB + j * 16),
                          srcb + (size_t)r * K + j * 8);
            }
        }
    };

    float acc[4][4][4];
    #pragma unroll
    for (int i = 0; i < 4; i++)
        #pragma unroll
        for (int j = 0; j < 4; j++)
            #pragma unroll
            for (int r = 0; r < 4; r++) acc[i][j][r] = 0.f;

    const int nch = K >> 6;            // always >= 16 here
    issue(0, 0); cp_commit();
    issue(1, 1); cp_commit();

    // ldmatrix address components (fixed per thread)
    const int arow_l = lane & 15;                     // A: row within 16
    const int acol_l = (lane >> 4) << 3;              // A: k-half select
    const int brow_l = (lane & 7) + ((lane >> 4) << 3); // B: row within 16 (two n8 tiles)
    const int bcol_l = ((lane >> 3) & 1) << 3;        // B: k-half select

    for (int c = 0; c < nch; ++c) {
        if (c + 1 < nch) cp_wait1(); else cp_wait0();
        __syncthreads();
        if (c + 2 < nch) { issue(c + 2, (c + 2) % NSTAGE); cp_commit(); }

        const uint32_t sb = smem_u32(sm + (c % NSTAGE) * STAGEB);
        #pragma unroll
        for (int ks = 0; ks < 4; ks++) {
            const int kb = ks * 16;
            uint32_t ah[4][4], al[4][4];
            #pragma unroll
            for (int fm = 0; fm < 4; fm++) {
                uint32_t ad = sb + (uint32_t)(warpM + fm * 16 + arow_l) * SROWB
                                 + (uint32_t)(kb + acol_l) * 2;
                ldmx4(ah[fm], ad);
                ldmx4(al[fm], ad + TILEB);
            }
            uint32_t bh[4][2], bl[4][2];
            #pragma unroll
            for (int fp = 0; fp < 2; fp++) {
                uint32_t bd = sb + 2 * TILEB
                                 + (uint32_t)(warpN + fp * 16 + brow_l) * SROWB
                                 + (uint32_t)(kb + bcol_l) * 2;
                uint32_t r4[4];
                ldmx4(r4, bd);
                bh[2*fp][0] = r4[0]; bh[2*fp][1] = r4[1];
                bh[2*fp+1][0] = r4[2]; bh[2*fp+1][1] = r4[3];
                ldmx4(r4, bd + TILEB);
                bl[2*fp][0] = r4[0]; bl[2*fp][1] = r4[1];
                bl[2*fp+1][0] = r4[2]; bl[2*fp+1][1] = r4[3];
            }
            // pass 1: hi*hi
            #pragma unroll
            for (int fm = 0; fm < 4; fm++)
                #pragma unroll
                for (int fn = 0; fn < 4; fn++)
                    mma_bf16(acc[fm][fn], ah[fm], bh[fn]);
            // pass 2: hi*lo
            #pragma unroll
            for (int fm = 0; fm < 4; fm++)
                #pragma unroll
                for (int fn = 0; fn < 4; fn++)
                    mma_bf16(acc[fm][fn], ah[fm], bl[fn]);
            // pass 3: lo*hi
            #pragma unroll
            for (int fm = 0; fm < 4; fm++)
                #pragma unroll
                for (int fn = 0; fn < 4; fn++)
                    mma_bf16(acc[fm][fn], al[fm], bh[fn]);
        }
    }

    #pragma unroll
    for (int fm = 0; fm < 4; fm++) {
        const int rbase = M0 + warpM + fm * 16 + g;
        #pragma unroll
        for (int half = 0; half < 2; half++) {
            const int row = rbase + half * 8;
            #pragma unroll
            for (int fn = 0; fn < 4; fn++) {
                const int col = N0 + warpN + fn * 8 + 2 * t;
                float v0 = acc[fm][fn][half * 2 + 0] + __ldg(&bias[col]);
                float v1 = acc[fm][fn][half * 2 + 1] + __ldg(&bias[col + 1]);
                if (RES) {
                    float2 rv = *(const float2*)(res + (size_t)row * N + col);
                    v0 += rv.x; v1 += rv.y;
                }
                if (RELU) { v0 = fmaxf(v0, 0.f); v1 = fmaxf(v1, 0.f); }
                if (SPLITOUT) {
                    __nv_bfloat16 h0,h1,l0,l1;
                    split_bf16(v0, h0, l0);
                    split_bf16(v1, h1, l1);
                    *(__nv_bfloat162*)(Ch + (size_t)row * N + col) = __nv_bfloat162{h0, h1};
                    *(__nv_bfloat162*)(Cl + (size_t)row * N + col) = __nv_bfloat162{l0, l1};
                } else {
                    *(float2*)(C + (size_t)row * N + col) = make_float2(v0, v1);
                }
            }
        }
    }
}

// ---------------------------------------------------------------- tensor-core flash attention
// grid (T/64, H, B), 128 thr (4 warps x m16 q-rows). BQ=64, BK=64, hd=64.
// qkv in split bf16 (hi/lo). Output ctx split bf16 into ch/cl.
#define KSTR 72   // smem row stride (bf16 elems): 144B, 16B-aligned, frag-conflict-free

__global__ __launch_bounds__(128)
void attn_mma_kernel(const __nv_bfloat16* __restrict__ qh_g, const __nv_bfloat16* __restrict__ ql_g,
                     const float* __restrict__ amask,
                     __nv_bfloat16* __restrict__ ch, __nv_bfloat16* __restrict__ cl) {
    const int q0 = blockIdx.x * 64;
    const int h = blockIdx.y, b = blockIdx.z;
    const int tid = threadIdx.x, lane = tid & 31, w = tid >> 5;
    const int g = lane >> 2, t = lane & 3;

    __shared__ alignas(16) __nv_bfloat16 Kh[64][KSTR], Kl[64][KSTR];
    __shared__ alignas(16) __nv_bfloat16 Vh[64][KSTR], Vl[64][KSTR];
    __shared__ float madd[64];

    // ---- Q fragments (once per block), rows w*16+g / +8 ----
    uint32_t qfh[4][4], qfl[4][4];
    {
        const size_t r0 = ((size_t)(b * TT + q0 + w * 16 + g)) * (3 * DD) + h * 64;
        const size_t r1 = r0 + (size_t)8 * (3 * DD);
        #pragma unroll
        for (int ks = 0; ks < 4; ks++) {
            int c = ks * 16 + 2 * t;
            qfh[ks][0] = *(const uint32_t*)(qh_g + r0 + c);
            qfh[ks][1] = *(const uint32_t*)(qh_g + r1 + c);
            qfh[ks][2] = *(const uint32_t*)(qh_g + r0 + c + 8);
            qfh[ks][3] = *(const uint32_t*)(qh_g + r1 + c + 8);
            qfl[ks][0] = *(const uint32_t*)(ql_g + r0 + c);
            qfl[ks][1] = *(const uint32_t*)(ql_g + r1 + c);
            qfl[ks][2] = *(const uint32_t*)(ql_g + r0 + c + 8);
            qfl[ks][3] = *(const uint32_t*)(ql_g + r1 + c + 8);
        }
    }

    float o[8][4];
    #pragma unroll
    for (int i = 0; i < 8; i++)
        #pragma unroll
        for (int j = 0; j < 4; j++) o[i][j] = 0.f;
    float m0 = -1e30f, m1 = -1e30f, l0 = 0.f, l1 = 0.f;

    for (int k0 = 0; k0 <= q0; k0 += 64) {
        // ---- load K, V tiles (split) via cp.async ----
        {
            const size_t gk = ((size_t)(b * TT + k0)) * (3 * DD) + DD + h * 64;
            const size_t gv = gk + DD;
            #pragma unroll
            for (int i = 0; i < 4; i++) {
                int cc = i * 128 + tid;
                int r = cc >> 3, j8 = (cc & 7) * 8;
                size_t rowoff = (size_t)r * (3 * DD) + j8;
                cpasync16(smem_u32(&Kh[r][j8]), qh_g + gk + rowoff);
                cpasync16(smem_u32(&Kl[r][j8]), ql_g + gk + rowoff);
                cpasync16(smem_u32(&Vh[r][j8]), qh_g + gv + rowoff);
                cpasync16(smem_u32(&Vl[r][j8]), ql_g + gv + rowoff);
            }
            cp_commit();
        }
        if (tid < 64) madd[tid] = (1.0f - __ldg(&amask[b * TT + k0 + tid])) * MASK_BIAS;
        cp_wait0();
        __syncthreads();

        // ---- S = Q K^T (bf16 x3, 3-pass ordering) ----
        float s[8][4];
        #pragma unroll
        for (int i = 0; i < 8; i++)
            #pragma unroll
            for (int j = 0; j < 4; j++) s[i][j] = 0.f;
        #pragma unroll
        for (int ks = 0; ks < 4; ks++) {
            const int kb = ks * 16 + 2 * t;
            uint32_t bh[8][2], bl[8][2];
            #pragma unroll
            for (int nt = 0; nt < 8; nt++) {
                const __nv_bfloat16* rp = &Kh[nt * 8 + g][kb];
                bh[nt][0] = *(const uint32_t*)(rp);
                bh[nt][1] = *(const uint32_t*)(rp + 8);
                const __nv_bfloat16* rq = &Kl[nt * 8 + g][kb];
                bl[nt][0] = *(const uint32_t*)(rq);
                bl[nt][1] = *(const uint32_t*)(rq + 8);
            }
            #pragma unroll
            for (int nt = 0; nt < 8; nt++) mma_bf16(s[nt], qfh[ks], bh[nt]);
            #pragma unroll
            for (int nt = 0; nt < 8; nt++) mma_bf16(s[nt], qfh[ks], bl[nt]);
            #pragma unroll
            for (int nt = 0; nt < 8; nt++) mma_bf16(s[nt], qfl[ks], bh[nt]);
        }

        // ---- scale + masks ----
        const int r0g = q0 + w * 16 + g, r1g = r0g + 8;
        const bool diag = (k0 == q0);
        #pragma unroll
        for (int nt = 0; nt < 8; nt++) {
            int c0 = nt * 8 + 2 * t, c1 = c0 + 1;
            float ma0 = madd[c0], ma1 = madd[c1];
            int gc0 = k0 + c0, gc1 = k0 + c1;
            float v;
            v = s[nt][0] * 0.125f; if (diag && gc0 > r0g) v = MASK_BIAS; s[nt][0] = v + ma0;
            v = s[nt][1] * 0.125f; if (diag && gc1 > r0g) v = MASK_BIAS; s[nt][1] = v + ma1;
            v = s[nt][2] * 0.125f; if (diag && gc0 > r1g) v = MASK_BIAS; s[nt][2] = v + ma0;
            v = s[nt][3] * 0.125f; if (diag && gc1 > r1g) v = MASK_BIAS; s[nt][3] = v + ma1;
        }

        // ---- online softmax (rows g, g+8; reduce over 4 lanes of quad) ----
        float rx0 = -1e30f, rx1 = -1e30f;
        #pragma unroll
        for (int nt = 0; nt < 8; nt++) {
            rx0 = fmaxf(rx0, fmaxf(s[nt][0], s[nt][1]));
            rx1 = fmaxf(rx1, fmaxf(s[nt][2], s[nt][3]));
        }
        rx0 = fmaxf(rx0, __shfl_xor_sync(0xffffffffu, rx0, 1));
        rx0 = fmaxf(rx0, __shfl_xor_sync(0xffffffffu, rx0, 2));
        rx1 = fmaxf(rx1, __shfl_xor_sync(0xffffffffu, rx1, 1));
        rx1 = fmaxf(rx1, __shfl_xor_sync(0xffffffffu, rx1, 2));
        float m0n = fmaxf(m0, rx0), m1n = fmaxf(m1, rx1);
        float a0 = __expf(m0 - m0n), a1 = __expf(m1 - m1n);
        float sum0 = 0.f, sum1 = 0.f;
        #pragma unroll
        for (int nt = 0; nt < 8; nt++) {
            s[nt][0] = __expf(s[nt][0] - m0n);
            s[nt][1] = __expf(s[nt][1] - m0n);
            s[nt][2] = __expf(s[nt][2] - m1n);
            s[nt][3] = __expf(s[nt][3] - m1n);
            sum0 += s[nt][0] + s[nt][1];
            sum1 += s[nt][2] + s[nt][3];
        }
        sum0 += __shfl_xor_sync(0xffffffffu, sum0, 1);
        sum0 += __shfl_xor_sync(0xffffffffu, sum0, 2);
        sum1 += __shfl_xor_sync(0xffffffffu, sum1, 1);
        sum1 += __shfl_xor_sync(0xffffffffu, sum1, 2);
        l0 = l0 * a0 + sum0; l1 = l1 * a1 + sum1;
        m0 = m0n; m1 = m1n;
        #pragma unroll
        for (int nt = 0; nt < 8; nt++) {
            o[nt][0] *= a0; o[nt][1] *= a0;
            o[nt][2] *= a1; o[nt][3] *= a1;
        }

        // ---- P fragments (split hi/lo) ----
        uint32_t ph[4][4], pl[4][4];
        #pragma unroll
        for (int j = 0; j < 4; j++) {
            float* pa = s[2 * j];
            float* pb = s[2 * j + 1];
            ph[j][0] = pack_bf16(pa[0], pa[1]);
            ph[j][1] = pack_bf16(pa[2], pa[3]);
            ph[j][2] = pack_bf16(pb[0], pb[1]);
            ph[j][3] = pack_bf16(pb[2], pb[3]);
            __nv_bfloat162 h0 = *(__nv_bfloat162*)&ph[j][0];
            __nv_bfloat162 h1 = *(__nv_bfloat162*)&ph[j][1];
            __nv_bfloat162 h2 = *(__nv_bfloat162*)&ph[j][2];
            __nv_bfloat162 h3 = *(__nv_bfloat162*)&ph[j][3];
            pl[j][0] = pack_bf16(pa[0] - __bfloat162float(h0.x), pa[1] - __bfloat162float(h0.y));
            pl[j][1] = pack_bf16(pa[2] - __bfloat162float(h1.x), pa[3] - __bfloat162float(h1.y));
            pl[j][2] = pack_bf16(pb[0] - __bfloat162float(h2.x), pb[1] - __bfloat162float(h2.y));
            pl[j][3] = pack_bf16(pb[2] - __bfloat162float(h3.x), pb[3] - __bfloat162float(h3.y));
        }

        // ---- O += P V (bf16 x3, 3-pass), V frags via ldmatrix.trans ----
        #pragma unroll
        for (int ks = 0; ks < 4; ks++) {
            uint32_t vh[8][2], vl[8][2];
            #pragma unroll
            for (int p2 = 0; p2 < 4; p2++) {
                int tile = lane >> 3, rown = lane & 7;
                int row = ks * 16 + (tile & 1) * 8 + rown;
                int col = (p2 * 2 + (tile >> 1)) * 8;
                uint32_t r4[4];
                ldmx4_trans(r4, smem_u32(&Vh[row][col]));
                vh[p2 * 2][0] = r4[0]; vh[p2 * 2][1] = r4[1];
                vh[p2 * 2 + 1][0] = r4[2]; vh[p2 * 2 + 1][1] = r4[3];
                ldmx4_trans(r4, smem_u32(&Vl[row][col]));
                vl[p2 * 2][0] = r4[0]; vl[p2 * 2][1] = r4[1];
                vl[p2 * 2 + 1][0] = r4[2]; vl[p2 * 2 + 1][1] = r4[3];
            }
            #pragma unroll
            for (int nt = 0; nt < 8; nt++) mma_bf16(o[nt], ph[ks], vh[nt]);
            #pragma unroll
            for (int nt = 0; nt < 8; nt++) mma_bf16(o[nt], ph[ks], vl[nt]);
            #pragma unroll
            for (int nt = 0; nt < 8; nt++) mma_bf16(o[nt], pl[ks], vh[nt]);
        }
        __syncthreads();
    }

    // ---- normalize + split-write ctx ----
    float inv0 = 1.f / l0, inv1 = 1.f / l1;
    const size_t ro0 = (size_t)(b * TT + q0 + w * 16 + g) * DD + h * 64;
    const size_t ro1 = ro0 + (size_t)8 * DD;
    #pragma unroll
    for (int nt = 0; nt < 8; nt++) {
        int c = nt * 8 + 2 * t;
        float v0 = o[nt][0] * inv0, v1 = o[nt][1] * inv0;
        float v2 = o[nt][2] * inv1, v3 = o[nt][3] * inv1;
        __nv_bfloat16 h0,h1,h2,h3,l0b,l1b,l2b,l3b;
        split_bf16(v0,h0,l0b); split_bf16(v1,h1,l1b);
        split_bf16(v2,h2,l2b); split_bf16(v3,h3,l3b);
        *(__nv_bfloat162*)(ch + ro0 + c) = __nv_bfloat162{h0, h1};
        *(__nv_bfloat162*)(cl + ro0 + c) = __nv_bfloat162{l0b, l1b};
        *(__nv_bfloat162*)(ch + ro1 + c) = __nv_bfloat162{h2, h3};
        *(__nv_bfloat162*)(cl + ro1 + c) = __nv_bfloat162{l2b, l3b};
    }
}

// ---------------------------------------------------------------- launch
extern "C" void kernel_launch(void* const* d_in, const int* in_sizes, int n_in,
                              void* d_out, int out_size) {
    const float* emb   = (const float*)d_in[0];
    const float* amask = (const float*)d_in[1];
    const float* ln1w  = (const float*)d_in[2];
    const float* ln1b  = (const float*)d_in[3];
    const float* attnw = (const float*)d_in[4];
    const float* attnb = (const float*)d_in[5];
    const float* projw = (const float*)d_in[6];
    const float* projb = (const float*)d_in[7];
    const float* ln2w  = (const float*)d_in[8];
    const float* ln2b  = (const float*)d_in[9];
    const float* fcw   = (const float*)d_in[10];
    const float* fcb   = (const float*)d_in[11];
    const float* fcpw  = (const float*)d_in[12];
    const float* fcpb  = (const float*)d_in[13];
    const float* lnfw  = (const float*)d_in[14];
    const float* lnfb  = (const float*)d_in[15];
    float* out = (float*)d_out;

    float *H;
    __nv_bfloat16 *Ah, *Al, *Fh, *Fl, *Wh, *Wl;
    cudaGetSymbolAddress((void**)&H,   g_H);
    cudaGetSymbolAddress((void**)&Ah,  g_Ah);
    cudaGetSymbolAddress((void**)&Al,  g_Al);
    cudaGetSymbolAddress((void**)&Fh,  g_Fh);
    cudaGetSymbolAddress((void**)&Fl,  g_Fl);
    cudaGetSymbolAddress((void**)&Wh,  g_Wh);
    cudaGetSymbolAddress((void**)&Wl,  g_Wl);

    cudaFuncSetAttribute(gemm_mma<false,false,true >, cudaFuncAttributeMaxDynamicSharedMemorySize, GSMEM);
    cudaFuncSetAttribute(gemm_mma<true, false,false>, cudaFuncAttributeMaxDynamicSharedMemorySize, GSMEM);
    cudaFuncSetAttribute(gemm_mma<false,true, true >, cudaFuncAttributeMaxDynamicSharedMemorySize, GSMEM);

    const int n4 = (MROWS * DD) / 4;
    copy_kernel<<<(n4 + 255) / 256, 256>>>((const float4*)emb, (float4*)H, n4);

    for (int l = 0; l < LL; l++) {
        const size_t wq = (size_t)l * DD * 3 * DD;
        const size_t wp = (size_t)l * DD * DD;
        const size_t wf = (size_t)l * DD * II;
        const size_t wg = (size_t)l * II * DD;

        // --- attention ---
        ln_split_kernel<<<MROWS, 256>>>(H, ln1w + l * DD, ln1b + l * DD, Ah, Al);
        splitT_kernel<<<dim3(3 * DD / 32, DD / 32), 256>>>(attnw + wq, Wh, Wl, DD, 3 * DD);
        gemm_mma<false,false,true><<<dim3(3 * DD / 128, MROWS / 128), 256, GSMEM>>>(
            Ah, Al, Wh, Wl, attnb + (size_t)l * 3 * DD, nullptr, nullptr, Fh, Fl, 3 * DD, DD);
        attn_mma_kernel<<<dim3(TT / 64, HH, BB), 128>>>(Fh, Fl, amask, Ah, Al);
        splitT_kernel<<<dim3(DD / 32, DD / 32), 256>>>(projw + wp, Wh, Wl, DD, DD);
        gemm_mma<true,false,false><<<dim3(DD / 128, MROWS / 128), 256, GSMEM>>>(
            Ah, Al, Wh, Wl, projb + (size_t)l * DD, H, H, nullptr, nullptr, DD, DD);

        // --- feed-forward ---
        ln_split_kernel<<<MROWS, 256>>>(H, ln2w + l * DD, ln2b + l * DD, Ah, Al);
        splitT_kernel<<<dim3(II / 32, DD / 32), 256>>>(fcw + wf, Wh, Wl, DD, II);
        gemm_mma<false,true,true><<<dim3(II / 128, MROWS / 128), 256, GSMEM>>>(
            Ah, Al, Wh, Wl, fcb + (size_t)l * II, nullptr, nullptr, Fh, Fl, II, DD);
        splitT_kernel<<<dim3(DD / 32, II / 32), 256>>>(fcpw + wg, Wh, Wl, II, DD);
        gemm_mma<true,false,false><<<dim3(DD / 128, MROWS / 128), 256, GSMEM>>>(
            Fh, Fl, Wh, Wl, fcpb + (size_t)l * DD, H, H, nullptr, nullptr, DD, II);
    }
    ln_kernel<<<MROWS, 256>>>(H, lnfw, lnfb, out);
}

// round 12
// speedup vs baseline: 1.6091x; 1.0183x over previous
#include <cuda_runtime.h>
#include <cuda_bf16.h>
#include <math.h>
#include <stdint.h>

#define BB 2
#define TT 2048
#define DD 1024
#define HH 16
#define LL 8
#define II 4096
#define MROWS (BB*TT)          // 4096
#define MASK_BIAS (-10000.0f)

// -------- scratch (no allocations allowed) --------
static __device__ float g_H  [(size_t)MROWS*DD];          // residual stream (f32)
static __device__ __nv_bfloat16 g_Ah[(size_t)MROWS*II];   // activation split hi (X / CTX)
static __device__ __nv_bfloat16 g_Al[(size_t)MROWS*II];   // activation split lo
static __device__ __nv_bfloat16 g_Fh[(size_t)MROWS*II];   // FF / QKV split hi
static __device__ __nv_bfloat16 g_Fl[(size_t)MROWS*II];   // FF / QKV split lo
static __device__ __nv_bfloat16 g_Wh[(size_t)II*DD];      // weight^T split hi [N x K]
static __device__ __nv_bfloat16 g_Wl[(size_t)II*DD];      // weight^T split lo

// ---------------------------------------------------------------- helpers
__device__ __forceinline__ uint32_t smem_u32(const void* p) {
    return (uint32_t)__cvta_generic_to_shared(p);
}

__device__ __forceinline__ void split_bf16(float x, __nv_bfloat16& h, __nv_bfloat16& l) {
    h = __float2bfloat16(x);
    l = __float2bfloat16(x - __bfloat162float(h));
}

__device__ __forceinline__ void mma_bf16(float* c, const uint32_t* a, const uint32_t* b) {
    asm volatile(
        "mma.sync.aligned.m16n8k16.row.col.f32.bf16.bf16.f32 "
        "{%0,%1,%2,%3},{%4,%5,%6,%7},{%8,%9},{%0,%1,%2,%3};"
        : "+f"(c[0]), "+f"(c[1]), "+f"(c[2]), "+f"(c[3])
        : "r"(a[0]), "r"(a[1]), "r"(a[2]), "r"(a[3]), "r"(b[0]), "r"(b[1]));
}

__device__ __forceinline__ void cpasync16(uint32_t dst, const void* src) {
    asm volatile("cp.async.cg.shared.global [%0], [%1], 16;" :: "r"(dst), "l"(src));
}
__device__ __forceinline__ void cp_commit() { asm volatile("cp.async.commit_group;"); }
__device__ __forceinline__ void cp_wait1()  { asm volatile("cp.async.wait_group 1;"); }
__device__ __forceinline__ void cp_wait0()  { asm volatile("cp.async.wait_group 0;"); }

__device__ __forceinline__ void ldmx4(uint32_t* r, uint32_t saddr) {
    asm volatile("ldmatrix.sync.aligned.m8n8.x4.shared.b16 {%0,%1,%2,%3}, [%4];"
        : "=r"(r[0]), "=r"(r[1]), "=r"(r[2]), "=r"(r[3]) : "r"(saddr));
}

__device__ __forceinline__ void ldmx4_trans(uint32_t* r, uint32_t saddr) {
    asm volatile("ldmatrix.sync.aligned.m8n8.x4.trans.shared.b16 {%0,%1,%2,%3}, [%4];"
        : "=r"(r[0]), "=r"(r[1]), "=r"(r[2]), "=r"(r[3]) : "r"(saddr));
}

__device__ __forceinline__ uint32_t pack_bf16(float x, float y) {
    __nv_bfloat162 v = __float22bfloat162_rn(float2{x, y});
    return *(uint32_t*)&v;
}

// ---------------------------------------------------------------- copy
__global__ void copy_kernel(const float4* __restrict__ src, float4* __restrict__ dst, int n4) {
    int i = blockIdx.x * blockDim.x + threadIdx.x;
    if (i < n4) dst[i] = src[i];
}

// ---------------------------------------------------------------- layernorm core (256 thr, D=1024)
__device__ __forceinline__ float4 ln_core(const float* __restrict__ in,
                                          const float* __restrict__ w,
                                          const float* __restrict__ bsc, int row, int t) {
    const float4* x4 = (const float4*)(in + (size_t)row * DD);
    float4 v = x4[t];
    float s = v.x + v.y + v.z + v.w;
    float q = v.x*v.x + v.y*v.y + v.z*v.z + v.w*v.w;
    #pragma unroll
    for (int o = 16; o; o >>= 1) {
        s += __shfl_xor_sync(0xffffffffu, s, o);
        q += __shfl_xor_sync(0xffffffffu, q, o);
    }
    __shared__ float ss[8], sq[8];
    __shared__ float red[2];
    int wid = t >> 5, lane = t & 31;
    if (lane == 0) { ss[wid] = s; sq[wid] = q; }
    __syncthreads();
    if (t == 0) {
        float S = 0.f, Q = 0.f;
        #pragma unroll
        for (int i = 0; i < 8; i++) { S += ss[i]; Q += sq[i]; }
        float mean = S * (1.0f / DD);
        float var  = Q * (1.0f / DD) - mean * mean;
        red[0] = mean;
        red[1] = rsqrtf(var + 1e-5f);
    }
    __syncthreads();
    float mean = red[0], inv = red[1];
    float4 wv = ((const float4*)w)[t];
    float4 bv = ((const float4*)bsc)[t];
    float4 o;
    o.x = (v.x - mean) * inv * wv.x + bv.x;
    o.y = (v.y - mean) * inv * wv.y + bv.y;
    o.z = (v.z - mean) * inv * wv.z + bv.z;
    o.w = (v.w - mean) * inv * wv.w + bv.w;
    return o;
}

__global__ void ln_kernel(const float* __restrict__ in, const float* __restrict__ w,
                          const float* __restrict__ bsc, float* __restrict__ out) {
    int row = blockIdx.x, t = threadIdx.x;
    float4 o = ln_core(in, w, bsc, row, t);
    ((float4*)(out + (size_t)row * DD))[t] = o;
}

__global__ void ln_split_kernel(const float* __restrict__ in, const float* __restrict__ w,
                                const float* __restrict__ bsc,
                                __nv_bfloat16* __restrict__ oh, __nv_bfloat16* __restrict__ ol) {
    int row = blockIdx.x, t = threadIdx.x;
    float4 o = ln_core(in, w, bsc, row, t);
    __nv_bfloat16 h0,h1,h2,h3,l0,l1,l2,l3;
    split_bf16(o.x,h0,l0); split_bf16(o.y,h1,l1); split_bf16(o.z,h2,l2); split_bf16(o.w,h3,l3);
    size_t idx = (size_t)row * DD + t * 4;
    *(__nv_bfloat162*)(oh + idx)     = __nv_bfloat162{h0,h1};
    *(__nv_bfloat162*)(oh + idx + 2) = __nv_bfloat162{h2,h3};
    *(__nv_bfloat162*)(ol + idx)     = __nv_bfloat162{l0,l1};
    *(__nv_bfloat162*)(ol + idx + 2) = __nv_bfloat162{l2,l3};
}

// ---------------------------------------------------------------- weight transpose + split
// W: [K x N] f32 row-major  ->  Th/Tl: [N x K] bf16
__global__ void splitT_kernel(const float* __restrict__ W, __nv_bfloat16* __restrict__ Th,
                              __nv_bfloat16* __restrict__ Tl, int K, int N) {
    __shared__ float t[32][33];
    int k0 = blockIdx.y * 32, n0 = blockIdx.x * 32;
    int tx = threadIdx.x & 31, ty = threadIdx.x >> 5;   // 8 rows per pass
    #pragma unroll
    for (int i = 0; i < 4; i++) {
        int r = ty + i * 8;
        t[r][tx] = W[(size_t)(k0 + r) * N + n0 + tx];
    }
    __syncthreads();
    #pragma unroll
    for (int i = 0; i < 4; i++) {
        int r = ty + i * 8;
        float v = t[tx][r];                 // = W[k0+tx][n0+r]
        __nv_bfloat16 h, l;
        split_bf16(v, h, l);
        size_t o = (size_t)(n0 + r) * K + k0 + tx;
        Th[o] = h; Tl[o] = l;
    }
}

// ---------------------------------------------------------------- bf16x3 mma.sync GEMM
// C[m][n] = sum_k A[m][k]*W[k][n] + bias (+res)(+relu). B operand = W^T [N x K] bf16.
// CTA 128x128, BK=32, 8 warps (2x4), warp tile 64x32.
// 2-stage cp.async pipeline, 80 KB smem -> 2 CTAs/SM (4 warps/SMSP),
// ldmatrix fragment loads, 3-pass compensation ordering.
#define SROWB   80                        // bytes per smem row (32 bf16 + 16 pad)
#define TILEB   (128 * SROWB)             // 10240 B
#define STAGEB  (4 * TILEB)               // 40960 B: Ah, Al, Bh, Bl
#define NSTAGE  2
#define GSMEM   (NSTAGE * STAGEB)         // 81920 B

template<bool RES, bool RELU, bool SPLITOUT>
__global__ __launch_bounds__(256, 2)
void gemm_mma(const __nv_bfloat16* __restrict__ Ah, const __nv_bfloat16* __restrict__ Al,
              const __nv_bfloat16* __restrict__ Bh, const __nv_bfloat16* __restrict__ Bl,
              const float* __restrict__ bias, const float* __restrict__ res,
              float* __restrict__ C, __nv_bfloat16* __restrict__ Ch, __nv_bfloat16* __restrict__ Cl,
              int N, int K) {
    extern __shared__ char sm[];
    const int tid = threadIdx.x, lane = tid & 31, wid = tid >> 5;
    const int g = lane >> 2, t = lane & 3;
    const int warpM = (wid >> 2) * 64, warpN = (wid & 3) * 32;
    const int M0 = blockIdx.y * 128, N0 = blockIdx.x * 128;

    const __nv_bfloat16* srcs[4] = {Ah, Al, Bh, Bl};
    const int bases[4] = {M0, M0, N0, N0};

    auto issue = [&](int c, int s) {
        const int k0 = c << 5;
        #pragma unroll
        for (int arr = 0; arr < 4; arr++) {
            char* dstb = sm + s * STAGEB + arr * TILEB;
            const __nv_bfloat16* srcb = srcs[arr] + (size_t)bases[arr] * K + k0;
            #pragma unroll
            for (int i = 0; i < 2; i++) {
                int cc = i * 256 + tid;
                int r = cc >> 2, j = cc & 3;
                cpasync16(smem_u32(dstb + r * SROWB + j * 16),
                          srcb + (size_t)r * K + j * 8);
            }
        }
    };

    float acc[4][4][4];
    #pragma unroll
    for (int i = 0; i < 4; i++)
        #pragma unroll
        for (int j = 0; j < 4; j++)
            #pragma unroll
            for (int r = 0; r < 4; r++) acc[i][j][r] = 0.f;

    const int nch = K >> 5;
    issue(0, 0); cp_commit();

    // ldmatrix address components (fixed per thread)
    const int arow_l = lane & 15;                       // A: row within 16
    const int acol_l = (lane >> 4) << 3;                // A: k-half select
    const int brow_l = (lane & 7) + ((lane >> 4) << 3); // B: row within 16 (two n8 tiles)
    const int bcol_l = ((lane >> 3) & 1) << 3;          // B: k-half select

    for (int c = 0; c < nch; ++c) {
        if (c + 1 < nch) { issue(c + 1, (c + 1) & 1); cp_commit(); cp_wait1(); }
        else cp_wait0();
        __syncthreads();

        const uint32_t sb = smem_u32(sm + (c & 1) * STAGEB);
        #pragma unroll
        for (int ks = 0; ks < 2; ks++) {
            const int kb = ks * 16;
            uint32_t ah[4][4], al[4][4];
            #pragma unroll
            for (int fm = 0; fm < 4; fm++) {
                uint32_t ad = sb + (uint32_t)(warpM + fm * 16 + arow_l) * SROWB
                                 + (uint32_t)(kb + acol_l) * 2;
                ldmx4(ah[fm], ad);
                ldmx4(al[fm], ad + TILEB);
            }
            uint32_t bh[4][2], bl[4][2];
            #pragma unroll
            for (int fp = 0; fp < 2; fp++) {
                uint32_t bd = sb + 2 * TILEB
                                 + (uint32_t)(warpN + fp * 16 + brow_l) * SROWB
                                 + (uint32_t)(kb + bcol_l) * 2;
                uint32_t r4[4];
                ldmx4(r4, bd);
                bh[2*fp][0] = r4[0]; bh[2*fp][1] = r4[1];
                bh[2*fp+1][0] = r4[2]; bh[2*fp+1][1] = r4[3];
                ldmx4(r4, bd + TILEB);
                bl[2*fp][0] = r4[0]; bl[2*fp][1] = r4[1];
                bl[2*fp+1][0] = r4[2]; bl[2*fp+1][1] = r4[3];
            }
            // pass 1: hi*hi
            #pragma unroll
            for (int fm = 0; fm < 4; fm++)
                #pragma unroll
                for (int fn = 0; fn < 4; fn++)
                    mma_bf16(acc[fm][fn], ah[fm], bh[fn]);
            // pass 2: hi*lo
            #pragma unroll
            for (int fm = 0; fm < 4; fm++)
                #pragma unroll
                for (int fn = 0; fn < 4; fn++)
                    mma_bf16(acc[fm][fn], ah[fm], bl[fn]);
            // pass 3: lo*hi
            #pragma unroll
            for (int fm = 0; fm < 4; fm++)
                #pragma unroll
                for (int fn = 0; fn < 4; fn++)
                    mma_bf16(acc[fm][fn], al[fm], bh[fn]);
        }
        __syncthreads();
    }

    #pragma unroll
    for (int fm = 0; fm < 4; fm++) {
        const int rbase = M0 + warpM + fm * 16 + g;
        #pragma unroll
        for (int half = 0; half < 2; half++) {
            const int row = rbase + half * 8;
            #pragma unroll
            for (int fn = 0; fn < 4; fn++) {
                const int col = N0 + warpN + fn * 8 + 2 * t;
                float v0 = acc[fm][fn][half * 2 + 0] + __ldg(&bias[col]);
                float v1 = acc[fm][fn][half * 2 + 1] + __ldg(&bias[col + 1]);
                if (RES) {
                    float2 rv = *(const float2*)(res + (size_t)row * N + col);
                    v0 += rv.x; v1 += rv.y;
                }
                if (RELU) { v0 = fmaxf(v0, 0.f); v1 = fmaxf(v1, 0.f); }
                if (SPLITOUT) {
                    __nv_bfloat16 h0,h1,l0,l1;
                    split_bf16(v0, h0, l0);
                    split_bf16(v1, h1, l1);
                    *(__nv_bfloat162*)(Ch + (size_t)row * N + col) = __nv_bfloat162{h0, h1};
                    *(__nv_bfloat162*)(Cl + (size_t)row * N + col) = __nv_bfloat162{l0, l1};
                } else {
                    *(float2*)(C + (size_t)row * N + col) = make_float2(v0, v1);
                }
            }
        }
    }
}

// ---------------------------------------------------------------- tensor-core flash attention
// grid (T/64, H, B), 128 thr (4 warps x m16 q-rows). BQ=64, BK=64, hd=64.
// qkv in split bf16 (hi/lo). Output ctx split bf16 into ch/cl.
#define KSTR 72   // smem row stride (bf16 elems): 144B, 16B-aligned, frag-conflict-free

__global__ __launch_bounds__(128)
void attn_mma_kernel(const __nv_bfloat16* __restrict__ qh_g, const __nv_bfloat16* __restrict__ ql_g,
                     const float* __restrict__ amask,
                     __nv_bfloat16* __restrict__ ch, __nv_bfloat16* __restrict__ cl) {
    const int q0 = blockIdx.x * 64;
    const int h = blockIdx.y, b = blockIdx.z;
    const int tid = threadIdx.x, lane = tid & 31, w = tid >> 5;
    const int g = lane >> 2, t = lane & 3;

    __shared__ alignas(16) __nv_bfloat16 Kh[64][KSTR], Kl[64][KSTR];
    __shared__ alignas(16) __nv_bfloat16 Vh[64][KSTR], Vl[64][KSTR];
    __shared__ float madd[64];

    // ---- Q fragments (once per block), rows w*16+g / +8 ----
    uint32_t qfh[4][4], qfl[4][4];
    {
        const size_t r0 = ((size_t)(b * TT + q0 + w * 16 + g)) * (3 * DD) + h * 64;
        const size_t r1 = r0 + (size_t)8 * (3 * DD);
        #pragma unroll
        for (int ks = 0; ks < 4; ks++) {
            int c = ks * 16 + 2 * t;
            qfh[ks][0] = *(const uint32_t*)(qh_g + r0 + c);
            qfh[ks][1] = *(const uint32_t*)(qh_g + r1 + c);
            qfh[ks][2] = *(const uint32_t*)(qh_g + r0 + c + 8);
            qfh[ks][3] = *(const uint32_t*)(qh_g + r1 + c + 8);
            qfl[ks][0] = *(const uint32_t*)(ql_g + r0 + c);
            qfl[ks][1] = *(const uint32_t*)(ql_g + r1 + c);
            qfl[ks][2] = *(const uint32_t*)(ql_g + r0 + c + 8);
            qfl[ks][3] = *(const uint32_t*)(ql_g + r1 + c + 8);
        }
    }

    float o[8][4];
    #pragma unroll
    for (int i = 0; i < 8; i++)
        #pragma unroll
        for (int j = 0; j < 4; j++) o[i][j] = 0.f;
    float m0 = -1e30f, m1 = -1e30f, l0 = 0.f, l1 = 0.f;

    for (int k0 = 0; k0 <= q0; k0 += 64) {
        // ---- load K, V tiles (split) via cp.async ----
        {
            const size_t gk = ((size_t)(b * TT + k0)) * (3 * DD) + DD + h * 64;
            const size_t gv = gk + DD;
            #pragma unroll
            for (int i = 0; i < 4; i++) {
                int cc = i * 128 + tid;
                int r = cc >> 3, j8 = (cc & 7) * 8;
                size_t rowoff = (size_t)r * (3 * DD) + j8;
                cpasync16(smem_u32(&Kh[r][j8]), qh_g + gk + rowoff);
                cpasync16(smem_u32(&Kl[r][j8]), ql_g + gk + rowoff);
                cpasync16(smem_u32(&Vh[r][j8]), qh_g + gv + rowoff);
                cpasync16(smem_u32(&Vl[r][j8]), ql_g + gv + rowoff);
            }
            cp_commit();
        }
        if (tid < 64) madd[tid] = (1.0f - __ldg(&amask[b * TT + k0 + tid])) * MASK_BIAS;
        cp_wait0();
        __syncthreads();

        // ---- S = Q K^T (bf16 x3, 3-pass ordering) ----
        float s[8][4];
        #pragma unroll
        for (int i = 0; i < 8; i++)
            #pragma unroll
            for (int j = 0; j < 4; j++) s[i][j] = 0.f;
        #pragma unroll
        for (int ks = 0; ks < 4; ks++) {
            const int kb = ks * 16 + 2 * t;
            uint32_t bh[8][2], bl[8][2];
            #pragma unroll
            for (int nt = 0; nt < 8; nt++) {
                const __nv_bfloat16* rp = &Kh[nt * 8 + g][kb];
                bh[nt][0] = *(const uint32_t*)(rp);
                bh[nt][1] = *(const uint32_t*)(rp + 8);
                const __nv_bfloat16* rq = &Kl[nt * 8 + g][kb];
                bl[nt][0] = *(const uint32_t*)(rq);
                bl[nt][1] = *(const uint32_t*)(rq + 8);
            }
            #pragma unroll
            for (int nt = 0; nt < 8; nt++) mma_bf16(s[nt], qfh[ks], bh[nt]);
            #pragma unroll
            for (int nt = 0; nt < 8; nt++) mma_bf16(s[nt], qfh[ks], bl[nt]);
            #pragma unroll
            for (int nt = 0; nt < 8; nt++) mma_bf16(s[nt], qfl[ks], bh[nt]);
        }

        // ---- scale + masks ----
        const int r0g = q0 + w * 16 + g, r1g = r0g + 8;
        const bool diag = (k0 == q0);
        #pragma unroll
        for (int nt = 0; nt < 8; nt++) {
            int c0 = nt * 8 + 2 * t, c1 = c0 + 1;
            float ma0 = madd[c0], ma1 = madd[c1];
            int gc0 = k0 + c0, gc1 = k0 + c1;
            float v;
            v = s[nt][0] * 0.125f; if (diag && gc0 > r0g) v = MASK_BIAS; s[nt][0] = v + ma0;
            v = s[nt][1] * 0.125f; if (diag && gc1 > r0g) v = MASK_BIAS; s[nt][1] = v + ma1;
            v = s[nt][2] * 0.125f; if (diag && gc0 > r1g) v = MASK_BIAS; s[nt][2] = v + ma0;
            v = s[nt][3] * 0.125f; if (diag && gc1 > r1g) v = MASK_BIAS; s[nt][3] = v + ma1;
        }

        // ---- online softmax (rows g, g+8; reduce over 4 lanes of quad) ----
        float rx0 = -1e30f, rx1 = -1e30f;
        #pragma unroll
        for (int nt = 0; nt < 8; nt++) {
            rx0 = fmaxf(rx0, fmaxf(s[nt][0], s[nt][1]));
            rx1 = fmaxf(rx1, fmaxf(s[nt][2], s[nt][3]));
        }
        rx0 = fmaxf(rx0, __shfl_xor_sync(0xffffffffu, rx0, 1));
        rx0 = fmaxf(rx0, __shfl_xor_sync(0xffffffffu, rx0, 2));
        rx1 = fmaxf(rx1, __shfl_xor_sync(0xffffffffu, rx1, 1));
        rx1 = fmaxf(rx1, __shfl_xor_sync(0xffffffffu, rx1, 2));
        float m0n = fmaxf(m0, rx0), m1n = fmaxf(m1, rx1);
        float a0 = __expf(m0 - m0n), a1 = __expf(m1 - m1n);
        float sum0 = 0.f, sum1 = 0.f;
        #pragma unroll
        for (int nt = 0; nt < 8; nt++) {
            s[nt][0] = __expf(s[nt][0] - m0n);
            s[nt][1] = __expf(s[nt][1] - m0n);
            s[nt][2] = __expf(s[nt][2] - m1n);
            s[nt][3] = __expf(s[nt][3] - m1n);
            sum0 += s[nt][0] + s[nt][1];
            sum1 += s[nt][2] + s[nt][3];
        }
        sum0 += __shfl_xor_sync(0xffffffffu, sum0, 1);
        sum0 += __shfl_xor_sync(0xffffffffu, sum0, 2);
        sum1 += __shfl_xor_sync(0xffffffffu, sum1, 1);
        sum1 += __shfl_xor_sync(0xffffffffu, sum1, 2);
        l0 = l0 * a0 + sum0; l1 = l1 * a1 + sum1;
        m0 = m0n; m1 = m1n;
        #pragma unroll
        for (int nt = 0; nt < 8; nt++) {
            o[nt][0] *= a0; o[nt][1] *= a0;
            o[nt][2] *= a1; o[nt][3] *= a1;
        }

        // ---- P fragments (split hi/lo) ----
        uint32_t ph[4][4], pl[4][4];
        #pragma unroll
        for (int j = 0; j < 4; j++) {
            float* pa = s[2 * j];
            float* pb = s[2 * j + 1];
            ph[j][0] = pack_bf16(pa[0], pa[1]);
            ph[j][1] = pack_bf16(pa[2], pa[3]);
            ph[j][2] = pack_bf16(pb[0], pb[1]);
            ph[j][3] = pack_bf16(pb[2], pb[3]);
            __nv_bfloat162 h0 = *(__nv_bfloat162*)&ph[j][0];
            __nv_bfloat162 h1 = *(__nv_bfloat162*)&ph[j][1];
            __nv_bfloat162 h2 = *(__nv_bfloat162*)&ph[j][2];
            __nv_bfloat162 h3 = *(__nv_bfloat162*)&ph[j][3];
            pl[j][0] = pack_bf16(pa[0] - __bfloat162float(h0.x), pa[1] - __bfloat162float(h0.y));
            pl[j][1] = pack_bf16(pa[2] - __bfloat162float(h1.x), pa[3] - __bfloat162float(h1.y));
            pl[j][2] = pack_bf16(pb[0] - __bfloat162float(h2.x), pb[1] - __bfloat162float(h2.y));
            pl[j][3] = pack_bf16(pb[2] - __bfloat162float(h3.x), pb[3] - __bfloat162float(h3.y));
        }

        // ---- O += P V (bf16 x3, 3-pass), V frags via ldmatrix.trans ----
        #pragma unroll
        for (int ks = 0; ks < 4; ks++) {
            uint32_t vh[8][2], vl[8][2];
            #pragma unroll
            for (int p2 = 0; p2 < 4; p2++) {
                int tile = lane >> 3, rown = lane & 7;
                int row = ks * 16 + (tile & 1) * 8 + rown;
                int col = (p2 * 2 + (tile >> 1)) * 8;
                uint32_t r4[4];
                ldmx4_trans(r4, smem_u32(&Vh[row][col]));
                vh[p2 * 2][0] = r4[0]; vh[p2 * 2][1] = r4[1];
                vh[p2 * 2 + 1][0] = r4[2]; vh[p2 * 2 + 1][1] = r4[3];
                ldmx4_trans(r4, smem_u32(&Vl[row][col]));
                vl[p2 * 2][0] = r4[0]; vl[p2 * 2][1] = r4[1];
                vl[p2 * 2 + 1][0] = r4[2]; vl[p2 * 2 + 1][1] = r4[3];
            }
            #pragma unroll
            for (int nt = 0; nt < 8; nt++) mma_bf16(o[nt], ph[ks], vh[nt]);
            #pragma unroll
            for (int nt = 0; nt < 8; nt++) mma_bf16(o[nt], ph[ks], vl[nt]);
            #pragma unroll
            for (int nt = 0; nt < 8; nt++) mma_bf16(o[nt], pl[ks], vh[nt]);
        }
        __syncthreads();
    }

    // ---- normalize + split-write ctx ----
    float inv0 = 1.f / l0, inv1 = 1.f / l1;
    const size_t ro0 = (size_t)(b * TT + q0 + w * 16 + g) * DD + h * 64;
    const size_t ro1 = ro0 + (size_t)8 * DD;
    #pragma unroll
    for (int nt = 0; nt < 8; nt++) {
        int c = nt * 8 + 2 * t;
        float v0 = o[nt][0] * inv0, v1 = o[nt][1] * inv0;
        float v2 = o[nt][2] * inv1, v3 = o[nt][3] * inv1;
        __nv_bfloat16 h0,h1,h2,h3,l0b,l1b,l2b,l3b;
        split_bf16(v0,h0,l0b); split_bf16(v1,h1,l1b);
        split_bf16(v2,h2,l2b); split_bf16(v3,h3,l3b);
        *(__nv_bfloat162*)(ch + ro0 + c) = __nv_bfloat162{h0, h1};
        *(__nv_bfloat162*)(cl + ro0 + c) = __nv_bfloat162{l0b, l1b};
        *(__nv_bfloat162*)(ch + ro1 + c) = __nv_bfloat162{h2, h3};
        *(__nv_bfloat162*)(cl + ro1 + c) = __nv_bfloat162{l2b, l3b};
    }
}

// ---------------------------------------------------------------- launch
extern "C" void kernel_launch(void* const* d_in, const int* in_sizes, int n_in,
                              void* d_out, int out_size) {
    const float* emb   = (const float*)d_in[0];
    const float* amask = (const float*)d_in[1];
    const float* ln1w  = (const float*)d_in[2];
    const float* ln1b  = (const float*)d_in[3];
    const float* attnw = (const float*)d_in[4];
    const float* attnb = (const float*)d_in[5];
    const float* projw = (const float*)d_in[6];
    const float* projb = (const float*)d_in[7];
    const float* ln2w  = (const float*)d_in[8];
    const float* ln2b  = (const float*)d_in[9];
    const float* fcw   = (const float*)d_in[10];
    const float* fcb   = (const float*)d_in[11];
    const float* fcpw  = (const float*)d_in[12];
    const float* fcpb  = (const float*)d_in[13];
    const float* lnfw  = (const float*)d_in[14];
    const float* lnfb  = (const float*)d_in[15];
    float* out = (float*)d_out;

    float *H;
    __nv_bfloat16 *Ah, *Al, *Fh, *Fl, *Wh, *Wl;
    cudaGetSymbolAddress((void**)&H,   g_H);
    cudaGetSymbolAddress((void**)&Ah,  g_Ah);
    cudaGetSymbolAddress((void**)&Al,  g_Al);
    cudaGetSymbolAddress((void**)&Fh,  g_Fh);
    cudaGetSymbolAddress((void**)&Fl,  g_Fl);
    cudaGetSymbolAddress((void**)&Wh,  g_Wh);
    cudaGetSymbolAddress((void**)&Wl,  g_Wl);

    cudaFuncSetAttribute(gemm_mma<false,false,true >, cudaFuncAttributeMaxDynamicSharedMemorySize, GSMEM);
    cudaFuncSetAttribute(gemm_mma<true, false,false>, cudaFuncAttributeMaxDynamicSharedMemorySize, GSMEM);
    cudaFuncSetAttribute(gemm_mma<false,true, true >, cudaFuncAttributeMaxDynamicSharedMemorySize, GSMEM);

    const int n4 = (MROWS * DD) / 4;
    copy_kernel<<<(n4 + 255) / 256, 256>>>((const float4*)emb, (float4*)H, n4);

    for (int l = 0; l < LL; l++) {
        const size_t wq = (size_t)l * DD * 3 * DD;
        const size_t wp = (size_t)l * DD * DD;
        const size_t wf = (size_t)l * DD * II;
        const size_t wg = (size_t)l * II * DD;

        // --- attention ---
        ln_split_kernel<<<MROWS, 256>>>(H, ln1w + l * DD, ln1b + l * DD, Ah, Al);
        splitT_kernel<<<dim3(3 * DD / 32, DD / 32), 256>>>(attnw + wq, Wh, Wl, DD, 3 * DD);
        gemm_mma<false,false,true><<<dim3(3 * DD / 128, MROWS / 128), 256, GSMEM>>>(
            Ah, Al, Wh, Wl, attnb + (size_t)l * 3 * DD, nullptr, nullptr, Fh, Fl, 3 * DD, DD);
        attn_mma_kernel<<<dim3(TT / 64, HH, BB), 128>>>(Fh, Fl, amask, Ah, Al);
        splitT_kernel<<<dim3(DD / 32, DD / 32), 256>>>(projw + wp, Wh, Wl, DD, DD);
        gemm_mma<true,false,false><<<dim3(DD / 128, MROWS / 128), 256, GSMEM>>>(
            Ah, Al, Wh, Wl, projb + (size_t)l * DD, H, H, nullptr, nullptr, DD, DD);

        // --- feed-forward ---
        ln_split_kernel<<<MROWS, 256>>>(H, ln2w + l * DD, ln2b + l * DD, Ah, Al);
        splitT_kernel<<<dim3(II / 32, DD / 32), 256>>>(fcw + wf, Wh, Wl, DD, II);
        gemm_mma<false,true,true><<<dim3(II / 128, MROWS / 128), 256, GSMEM>>>(
            Ah, Al, Wh, Wl, fcb + (size_t)l * II, nullptr, nullptr, Fh, Fl, II, DD);
        splitT_kernel<<<dim3(DD / 32, II / 32), 256>>>(fcpw + wg, Wh, Wl, II, DD);
        gemm_mma<true,false,false><<<dim3(DD / 128, MROWS / 128), 256, GSMEM>>>(
            Fh, Fl, Wh, Wl, fcpb + (size_t)l * DD, H, H, nullptr, nullptr, DD, II);
    }
    ln_kernel<<<MROWS, 256>>>(H, lnfw, lnfb, out);
}

// round 14
// speedup vs baseline: 1.9944x; 1.2395x over previous
#include <cuda_runtime.h>
#include <cuda_bf16.h>
#include <cuda_fp16.h>
#include <math.h>
#include <stdint.h>

#define BB 2
#define TT 2048
#define DD 1024
#define HH 16
#define LL 8
#define II 4096
#define MROWS (BB*TT)          // 4096
#define MASK_BIAS (-10000.0f)

// -------- scratch (no allocations allowed) --------
static __device__ float g_H  [(size_t)MROWS*DD];          // residual stream (f32)
static __device__ __nv_bfloat16 g_Ah[(size_t)MROWS*II];   // activation split hi (16-bit, type-punned)
static __device__ __nv_bfloat16 g_Al[(size_t)MROWS*II];   // activation split lo
static __device__ __nv_bfloat16 g_Fh[(size_t)MROWS*II];   // FF / QKV split hi
static __device__ __nv_bfloat16 g_Fl[(size_t)MROWS*II];   // FF / QKV split lo
static __device__ __nv_bfloat16 g_Wh[(size_t)II*DD];      // weight^T hi [N x K]
static __device__ __nv_bfloat16 g_Wl[(size_t)II*DD];      // weight^T lo

// ---------------------------------------------------------------- helpers
__device__ __forceinline__ uint32_t smem_u32(const void* p) {
    return (uint32_t)__cvta_generic_to_shared(p);
}

__device__ __forceinline__ void split_bf16(float x, __nv_bfloat16& h, __nv_bfloat16& l) {
    h = __float2bfloat16(x);
    l = __float2bfloat16(x - __bfloat162float(h));
}
__device__ __forceinline__ void split_f16(float x, __half& h, __half& l) {
    h = __float2half_rn(x);
    l = __float2half_rn(x - __half2float(h));
}

__device__ __forceinline__ void mma_bf16(float* c, const uint32_t* a, const uint32_t* b) {
    asm volatile(
        "mma.sync.aligned.m16n8k16.row.col.f32.bf16.bf16.f32 "
        "{%0,%1,%2,%3},{%4,%5,%6,%7},{%8,%9},{%0,%1,%2,%3};"
        : "+f"(c[0]), "+f"(c[1]), "+f"(c[2]), "+f"(c[3])
        : "r"(a[0]), "r"(a[1]), "r"(a[2]), "r"(a[3]), "r"(b[0]), "r"(b[1]));
}
__device__ __forceinline__ void mma_f16(float* c, const uint32_t* a, const uint32_t* b) {
    asm volatile(
        "mma.sync.aligned.m16n8k16.row.col.f32.f16.f16.f32 "
        "{%0,%1,%2,%3},{%4,%5,%6,%7},{%8,%9},{%0,%1,%2,%3};"
        : "+f"(c[0]), "+f"(c[1]), "+f"(c[2]), "+f"(c[3])
        : "r"(a[0]), "r"(a[1]), "r"(a[2]), "r"(a[3]), "r"(b[0]), "r"(b[1]));
}

__device__ __forceinline__ void cpasync16(uint32_t dst, const void* src) {
    asm volatile("cp.async.cg.shared.global [%0], [%1], 16;" :: "r"(dst), "l"(src));
}
__device__ __forceinline__ void cp_commit() { asm volatile("cp.async.commit_group;"); }
__device__ __forceinline__ void cp_wait1()  { asm volatile("cp.async.wait_group 1;"); }
__device__ __forceinline__ void cp_wait0()  { asm volatile("cp.async.wait_group 0;"); }

__device__ __forceinline__ void ldmx4(uint32_t* r, uint32_t saddr) {
    asm volatile("ldmatrix.sync.aligned.m8n8.x4.shared.b16 {%0,%1,%2,%3}, [%4];"
        : "=r"(r[0]), "=r"(r[1]), "=r"(r[2]), "=r"(r[3]) : "r"(saddr));
}
__device__ __forceinline__ void ldmx4_trans(uint32_t* r, uint32_t saddr) {
    asm volatile("ldmatrix.sync.aligned.m8n8.x4.trans.shared.b16 {%0,%1,%2,%3}, [%4];"
        : "=r"(r[0]), "=r"(r[1]), "=r"(r[2]), "=r"(r[3]) : "r"(saddr));
}

__device__ __forceinline__ uint32_t pack_f16(float x, float y) {
    __half2 v = __floats2half2_rn(x, y);
    return *(uint32_t*)&v;
}

// ---------------------------------------------------------------- copy
__global__ void copy_kernel(const float4* __restrict__ src, float4* __restrict__ dst, int n4) {
    int i = blockIdx.x * blockDim.x + threadIdx.x;
    if (i < n4) dst[i] = src[i];
}

// ---------------------------------------------------------------- layernorm core (256 thr, D=1024)
__device__ __forceinline__ float4 ln_core(const float* __restrict__ in,
                                          const float* __restrict__ w,
                                          const float* __restrict__ bsc, int row, int t) {
    const float4* x4 = (const float4*)(in + (size_t)row * DD);
    float4 v = x4[t];
    float s = v.x + v.y + v.z + v.w;
    float q = v.x*v.x + v.y*v.y + v.z*v.z + v.w*v.w;
    #pragma unroll
    for (int o = 16; o; o >>= 1) {
        s += __shfl_xor_sync(0xffffffffu, s, o);
        q += __shfl_xor_sync(0xffffffffu, q, o);
    }
    __shared__ float ss[8], sq[8];
    __shared__ float red[2];
    int wid = t >> 5, lane = t & 31;
    if (lane == 0) { ss[wid] = s; sq[wid] = q; }
    __syncthreads();
    if (t == 0) {
        float S = 0.f, Q = 0.f;
        #pragma unroll
        for (int i = 0; i < 8; i++) { S += ss[i]; Q += sq[i]; }
        float mean = S * (1.0f / DD);
        float var  = Q * (1.0f / DD) - mean * mean;
        red[0] = mean;
        red[1] = rsqrtf(var + 1e-5f);
    }
    __syncthreads();
    float mean = red[0], inv = red[1];
    float4 wv = ((const float4*)w)[t];
    float4 bv = ((const float4*)bsc)[t];
    float4 o;
    o.x = (v.x - mean) * inv * wv.x + bv.x;
    o.y = (v.y - mean) * inv * wv.y + bv.y;
    o.z = (v.z - mean) * inv * wv.z + bv.z;
    o.w = (v.w - mean) * inv * wv.w + bv.w;
    return o;
}

__global__ void ln_kernel(const float* __restrict__ in, const float* __restrict__ w,
                          const float* __restrict__ bsc, float* __restrict__ out) {
    int row = blockIdx.x, t = threadIdx.x;
    float4 o = ln_core(in, w, bsc, row, t);
    ((float4*)(out + (size_t)row * DD))[t] = o;
}

__global__ void ln_split_f16_kernel(const float* __restrict__ in, const float* __restrict__ w,
                                    const float* __restrict__ bsc,
                                    __half* __restrict__ oh, __half* __restrict__ ol) {
    int row = blockIdx.x, t = threadIdx.x;
    float4 o = ln_core(in, w, bsc, row, t);
    __half h0,h1,h2,h3,l0,l1,l2,l3;
    split_f16(o.x,h0,l0); split_f16(o.y,h1,l1); split_f16(o.z,h2,l2); split_f16(o.w,h3,l3);
    size_t idx = (size_t)row * DD + t * 4;
    *(__half2*)(oh + idx)     = __half2{h0,h1};
    *(__half2*)(oh + idx + 2) = __half2{h2,h3};
    *(__half2*)(ol + idx)     = __half2{l0,l1};
    *(__half2*)(ol + idx + 2) = __half2{l2,l3};
}

// ---------------------------------------------------------------- weight transpose + split
// W: [K x N] f32 row-major  ->  Th/Tl: [N x K] bf16 (3-term path)
__global__ void splitT_kernel(const float* __restrict__ W, __nv_bfloat16* __restrict__ Th,
                              __nv_bfloat16* __restrict__ Tl, int K, int N) {
    __shared__ float t[32][33];
    int k0 = blockIdx.y * 32, n0 = blockIdx.x * 32;
    int tx = threadIdx.x & 31, ty = threadIdx.x >> 5;
    #pragma unroll
    for (int i = 0; i < 4; i++) {
        int r = ty + i * 8;
        t[r][tx] = W[(size_t)(k0 + r) * N + n0 + tx];
    }
    __syncthreads();
    #pragma unroll
    for (int i = 0; i < 4; i++) {
        int r = ty + i * 8;
        float v = t[tx][r];
        __nv_bfloat16 h, l;
        split_bf16(v, h, l);
        size_t o = (size_t)(n0 + r) * K + k0 + tx;
        Th[o] = h; Tl[o] = l;
    }
}

// W: [K x N] f32 -> Th: [N x K] single fp16 (2-term path)
__global__ void splitT_f16_kernel(const float* __restrict__ W, __half* __restrict__ Th,
                                  int K, int N) {
    __shared__ float t[32][33];
    int k0 = blockIdx.y * 32, n0 = blockIdx.x * 32;
    int tx = threadIdx.x & 31, ty = threadIdx.x >> 5;
    #pragma unroll
    for (int i = 0; i < 4; i++) {
        int r = ty + i * 8;
        t[r][tx] = W[(size_t)(k0 + r) * N + n0 + tx];
    }
    __syncthreads();
    #pragma unroll
    for (int i = 0; i < 4; i++) {
        int r = ty + i * 8;
        Th[(size_t)(n0 + r) * K + k0 + tx] = __float2half_rn(t[tx][r]);
    }
}

// ---------------------------------------------------------------- shared GEMM geometry
#define SROWB   80                        // bytes per smem row (32 x 16-bit + 16 pad)
#define TILEB   (128 * SROWB)             // 10240 B
#define STAGEB  (4 * TILEB)               // bf16x3: Ah, Al, Bh, Bl
#define GSMEM   (2 * STAGEB)              // 81920 B
#define STAGEB2 (3 * TILEB)               // fp16x2: Ah, Al, Bh
#define GSMEM2  (2 * STAGEB2)             // 61440 B

// ---------------------------------------------------------------- bf16x3 GEMM (proj / fcp)
// C[m][n] = sum_k A[m][k]*W[k][n] + bias + res. 128x128 CTA, BK=32, 2 CTAs/SM.
__global__ __launch_bounds__(256, 2)
void gemm_mma3(const __nv_bfloat16* __restrict__ Ah, const __nv_bfloat16* __restrict__ Al,
               const __nv_bfloat16* __restrict__ Bh, const __nv_bfloat16* __restrict__ Bl,
               const float* __restrict__ bias, const float* __restrict__ res,
               float* __restrict__ C, int N, int K) {
    extern __shared__ char sm[];
    const int tid = threadIdx.x, lane = tid & 31, wid = tid >> 5;
    const int g = lane >> 2, t = lane & 3;
    const int warpM = (wid >> 2) * 64, warpN = (wid & 3) * 32;
    const int M0 = blockIdx.y * 128, N0 = blockIdx.x * 128;

    const __nv_bfloat16* srcs[4] = {Ah, Al, Bh, Bl};
    const int bases[4] = {M0, M0, N0, N0};

    auto issue = [&](int c, int s) {
        const int k0 = c << 5;
        #pragma unroll
        for (int arr = 0; arr < 4; arr++) {
            char* dstb = sm + s * STAGEB + arr * TILEB;
            const __nv_bfloat16* srcb = srcs[arr] + (size_t)bases[arr] * K + k0;
            #pragma unroll
            for (int i = 0; i < 2; i++) {
                int cc = i * 256 + tid;
                int r = cc >> 2, j = cc & 3;
                cpasync16(smem_u32(dstb + r * SROWB + j * 16),
                          srcb + (size_t)r * K + j * 8);
            }
        }
    };

    float acc[4][4][4];
    #pragma unroll
    for (int i = 0; i < 4; i++)
        #pragma unroll
        for (int j = 0; j < 4; j++)
            #pragma unroll
            for (int r = 0; r < 4; r++) acc[i][j][r] = 0.f;

    const int nch = K >> 5;
    issue(0, 0); cp_commit();

    const int arow_l = lane & 15;
    const int acol_l = (lane >> 4) << 3;
    const int brow_l = (lane & 7) + ((lane >> 4) << 3);
    const int bcol_l = ((lane >> 3) & 1) << 3;

    for (int c = 0; c < nch; ++c) {
        if (c + 1 < nch) { issue(c + 1, (c + 1) & 1); cp_commit(); cp_wait1(); }
        else cp_wait0();
        __syncthreads();

        const uint32_t sb = smem_u32(sm + (c & 1) * STAGEB);
        #pragma unroll
        for (int ks = 0; ks < 2; ks++) {
            const int kb = ks * 16;
            uint32_t ah[4][4], al[4][4];
            #pragma unroll
            for (int fm = 0; fm < 4; fm++) {
                uint32_t ad = sb + (uint32_t)(warpM + fm * 16 + arow_l) * SROWB
                                 + (uint32_t)(kb + acol_l) * 2;
                ldmx4(ah[fm], ad);
                ldmx4(al[fm], ad + TILEB);
            }
            uint32_t bh[4][2], bl[4][2];
            #pragma unroll
            for (int fp = 0; fp < 2; fp++) {
                uint32_t bd = sb + 2 * TILEB
                                 + (uint32_t)(warpN + fp * 16 + brow_l) * SROWB
                                 + (uint32_t)(kb + bcol_l) * 2;
                uint32_t r4[4];
                ldmx4(r4, bd);
                bh[2*fp][0] = r4[0]; bh[2*fp][1] = r4[1];
                bh[2*fp+1][0] = r4[2]; bh[2*fp+1][1] = r4[3];
                ldmx4(r4, bd + TILEB);
                bl[2*fp][0] = r4[0]; bl[2*fp][1] = r4[1];
                bl[2*fp+1][0] = r4[2]; bl[2*fp+1][1] = r4[3];
            }
            #pragma unroll
            for (int fm = 0; fm < 4; fm++)
                #pragma unroll
                for (int fn = 0; fn < 4; fn++)
                    mma_bf16(acc[fm][fn], ah[fm], bh[fn]);
            #pragma unroll
            for (int fm = 0; fm < 4; fm++)
                #pragma unroll
                for (int fn = 0; fn < 4; fn++)
                    mma_bf16(acc[fm][fn], ah[fm], bl[fn]);
            #pragma unroll
            for (int fm = 0; fm < 4; fm++)
                #pragma unroll
                for (int fn = 0; fn < 4; fn++)
                    mma_bf16(acc[fm][fn], al[fm], bh[fn]);
        }
        __syncthreads();
    }

    #pragma unroll
    for (int fm = 0; fm < 4; fm++) {
        const int rbase = M0 + warpM + fm * 16 + g;
        #pragma unroll
        for (int half = 0; half < 2; half++) {
            const int row = rbase + half * 8;
            #pragma unroll
            for (int fn = 0; fn < 4; fn++) {
                const int col = N0 + warpN + fn * 8 + 2 * t;
                float v0 = acc[fm][fn][half * 2 + 0] + __ldg(&bias[col]);
                float v1 = acc[fm][fn][half * 2 + 1] + __ldg(&bias[col + 1]);
                float2 rv = *(const float2*)(res + (size_t)row * N + col);
                v0 += rv.x; v1 += rv.y;
                *(float2*)(C + (size_t)row * N + col) = make_float2(v0, v1);
            }
        }
    }
}

// ---------------------------------------------------------------- fp16x2 GEMM (QKV / fc)
// A split fp16 hi/lo, B single fp16. Output: split pair (fp16 if OUTF16 else bf16), +RELU opt.
template<bool RELU, bool OUTF16>
__global__ __launch_bounds__(256, 2)
void gemm_mma2(const __half* __restrict__ Ah, const __half* __restrict__ Al,
               const __half* __restrict__ Bh,
               const float* __restrict__ bias,
               void* __restrict__ Ch_, void* __restrict__ Cl_, int N, int K) {
    extern __shared__ char sm[];
    const int tid = threadIdx.x, lane = tid & 31, wid = tid >> 5;
    const int g = lane >> 2, t = lane & 3;
    const int warpM = (wid >> 2) * 64, warpN = (wid & 3) * 32;
    const int M0 = blockIdx.y * 128, N0 = blockIdx.x * 128;

    const __half* srcs[3] = {Ah, Al, Bh};
    const int bases[3] = {M0, M0, N0};

    auto issue = [&](int c, int s) {
        const int k0 = c << 5;
        #pragma unroll
        for (int arr = 0; arr < 3; arr++) {
            char* dstb = sm + s * STAGEB2 + arr * TILEB;
            const __half* srcb = srcs[arr] + (size_t)bases[arr] * K + k0;
            #pragma unroll
            for (int i = 0; i < 2; i++) {
                int cc = i * 256 + tid;
                int r = cc >> 2, j = cc & 3;
                cpasync16(smem_u32(dstb + r * SROWB + j * 16),
                          srcb + (size_t)r * K + j * 8);
            }
        }
    };

    float acc[4][4][4];
    #pragma unroll
    for (int i = 0; i < 4; i++)
        #pragma unroll
        for (int j = 0; j < 4; j++)
            #pragma unroll
            for (int r = 0; r < 4; r++) acc[i][j][r] = 0.f;

    const int nch = K >> 5;
    issue(0, 0); cp_commit();

    const int arow_l = lane & 15;
    const int acol_l = (lane >> 4) << 3;
    const int brow_l = (lane & 7) + ((lane >> 4) << 3);
    const int bcol_l = ((lane >> 3) & 1) << 3;

    for (int c = 0; c < nch; ++c) {
        if (c + 1 < nch) { issue(c + 1, (c + 1) & 1); cp_commit(); cp_wait1(); }
        else cp_wait0();
        __syncthreads();

        const uint32_t sb = smem_u32(sm + (c & 1) * STAGEB2);
        #pragma unroll
        for (int ks = 0; ks < 2; ks++) {
            const int kb = ks * 16;
            uint32_t ah[4][4], al[4][4];
            #pragma unroll
            for (int fm = 0; fm < 4; fm++) {
                uint32_t ad = sb + (uint32_t)(warpM + fm * 16 + arow_l) * SROWB
                                 + (uint32_t)(kb + acol_l) * 2;
                ldmx4(ah[fm], ad);
                ldmx4(al[fm], ad + TILEB);
            }
            uint32_t bh[4][2];
            #pragma unroll
            for (int fp = 0; fp < 2; fp++) {
                uint32_t bd = sb + 2 * TILEB
                                 + (uint32_t)(warpN + fp * 16 + brow_l) * SROWB
                                 + (uint32_t)(kb + bcol_l) * 2;
                uint32_t r4[4];
                ldmx4(r4, bd);
                bh[2*fp][0] = r4[0]; bh[2*fp][1] = r4[1];
                bh[2*fp+1][0] = r4[2]; bh[2*fp+1][1] = r4[3];
            }
            #pragma unroll
            for (int fm = 0; fm < 4; fm++)
                #pragma unroll
                for (int fn = 0; fn < 4; fn++)
                    mma_f16(acc[fm][fn], ah[fm], bh[fn]);
            #pragma unroll
            for (int fm = 0; fm < 4; fm++)
                #pragma unroll
                for (int fn = 0; fn < 4; fn++)
                    mma_f16(acc[fm][fn], al[fm], bh[fn]);
        }
        __syncthreads();
    }

    #pragma unroll
    for (int fm = 0; fm < 4; fm++) {
        const int rbase = M0 + warpM + fm * 16 + g;
        #pragma unroll
        for (int half = 0; half < 2; half++) {
            const int row = rbase + half * 8;
            #pragma unroll
            for (int fn = 0; fn < 4; fn++) {
                const int col = N0 + warpN + fn * 8 + 2 * t;
                float v0 = acc[fm][fn][half * 2 + 0] + __ldg(&bias[col]);
                float v1 = acc[fm][fn][half * 2 + 1] + __ldg(&bias[col + 1]);
                if (RELU) { v0 = fmaxf(v0, 0.f); v1 = fmaxf(v1, 0.f); }
                if (OUTF16) {
                    __half h0,h1,l0,l1;
                    split_f16(v0, h0, l0);
                    split_f16(v1, h1, l1);
                    *(__half2*)((__half*)Ch_ + (size_t)row * N + col) = __half2{h0, h1};
                    *(__half2*)((__half*)Cl_ + (size_t)row * N + col) = __half2{l0, l1};
                } else {
                    __nv_bfloat16 h0,h1,l0,l1;
                    split_bf16(v0, h0, l0);
                    split_bf16(v1, h1, l1);
                    *(__nv_bfloat162*)((__nv_bfloat16*)Ch_ + (size_t)row * N + col) = __nv_bfloat162{h0, h1};
                    *(__nv_bfloat162*)((__nv_bfloat16*)Cl_ + (size_t)row * N + col) = __nv_bfloat162{l0, l1};
                }
            }
        }
    }
}

// ---------------------------------------------------------------- tensor-core flash attention (fp16 x2)
// grid (T/64, H, B), 128 thr. BQ=64, BK=64, hd=64.
// qkv split fp16 (Q uses hi+lo, K/V hi only). Output ctx split bf16 into ch/cl.
#define KSTR 72

__global__ __launch_bounds__(128)
void attn_mma_kernel(const __half* __restrict__ qh_g, const __half* __restrict__ ql_g,
                     const float* __restrict__ amask,
                     __nv_bfloat16* __restrict__ ch, __nv_bfloat16* __restrict__ cl) {
    const int q0 = blockIdx.x * 64;
    const int h = blockIdx.y, b = blockIdx.z;
    const int tid = threadIdx.x, lane = tid & 31, w = tid >> 5;
    const int g = lane >> 2, t = lane & 3;

    __shared__ alignas(16) __half Kh[64][KSTR];
    __shared__ alignas(16) __half Vh[64][KSTR];
    __shared__ float madd[64];

    // ---- Q fragments (once per block), rows w*16+g / +8 ----
    uint32_t qfh[4][4], qfl[4][4];
    {
        const size_t r0 = ((size_t)(b * TT + q0 + w * 16 + g)) * (3 * DD) + h * 64;
        const size_t r1 = r0 + (size_t)8 * (3 * DD);
        #pragma unroll
        for (int ks = 0; ks < 4; ks++) {
            int c = ks * 16 + 2 * t;
            qfh[ks][0] = *(const uint32_t*)(qh_g + r0 + c);
            qfh[ks][1] = *(const uint32_t*)(qh_g + r1 + c);
            qfh[ks][2] = *(const uint32_t*)(qh_g + r0 + c + 8);
            qfh[ks][3] = *(const uint32_t*)(qh_g + r1 + c + 8);
            qfl[ks][0] = *(const uint32_t*)(ql_g + r0 + c);
            qfl[ks][1] = *(const uint32_t*)(ql_g + r1 + c);
            qfl[ks][2] = *(const uint32_t*)(ql_g + r0 + c + 8);
            qfl[ks][3] = *(const uint32_t*)(ql_g + r1 + c + 8);
        }
    }

    float o[8][4];
    #pragma unroll
    for (int i = 0; i < 8; i++)
        #pragma unroll
        for (int j = 0; j < 4; j++) o[i][j] = 0.f;
    float m0 = -1e30f, m1 = -1e30f, l0 = 0.f, l1 = 0.f;

    for (int k0 = 0; k0 <= q0; k0 += 64) {
        // ---- load K, V hi tiles via cp.async ----
        {
            const size_t gk = ((size_t)(b * TT + k0)) * (3 * DD) + DD + h * 64;
            const size_t gv = gk + DD;
            #pragma unroll
            for (int i = 0; i < 4; i++) {
                int cc = i * 128 + tid;
                int r = cc >> 3, j8 = (cc & 7) * 8;
                size_t rowoff = (size_t)r * (3 * DD) + j8;
                cpasync16(smem_u32(&Kh[r][j8]), qh_g + gk + rowoff);
                cpasync16(smem_u32(&Vh[r][j8]), qh_g + gv + rowoff);
            }
            cp_commit();
        }
        if (tid < 64) madd[tid] = (1.0f - __ldg(&amask[b * TT + k0 + tid])) * MASK_BIAS;
        cp_wait0();
        __syncthreads();

        // ---- S = Q K^T (fp16 x2) ----
        float s[8][4];
        #pragma unroll
        for (int i = 0; i < 8; i++)
            #pragma unroll
            for (int j = 0; j < 4; j++) s[i][j] = 0.f;
        #pragma unroll
        for (int ks = 0; ks < 4; ks++) {
            const int kb = ks * 16 + 2 * t;
            uint32_t bh[8][2];
            #pragma unroll
            for (int nt = 0; nt < 8; nt++) {
                const __half* rp = &Kh[nt * 8 + g][kb];
                bh[nt][0] = *(const uint32_t*)(rp);
                bh[nt][1] = *(const uint32_t*)(rp + 8);
            }
            #pragma unroll
            for (int nt = 0; nt < 8; nt++) mma_f16(s[nt], qfh[ks], bh[nt]);
            #pragma unroll
            for (int nt = 0; nt < 8; nt++) mma_f16(s[nt], qfl[ks], bh[nt]);
        }

        // ---- scale + masks ----
        const int r0g = q0 + w * 16 + g, r1g = r0g + 8;
        const bool diag = (k0 == q0);
        #pragma unroll
        for (int nt = 0; nt < 8; nt++) {
            int c0 = nt * 8 + 2 * t, c1 = c0 + 1;
            float ma0 = madd[c0], ma1 = madd[c1];
            int gc0 = k0 + c0, gc1 = k0 + c1;
            float v;
            v = s[nt][0] * 0.125f; if (diag && gc0 > r0g) v = MASK_BIAS; s[nt][0] = v + ma0;
            v = s[nt][1] * 0.125f; if (diag && gc1 > r0g) v = MASK_BIAS; s[nt][1] = v + ma1;
            v = s[nt][2] * 0.125f; if (diag && gc0 > r1g) v = MASK_BIAS; s[nt][2] = v + ma0;
            v = s[nt][3] * 0.125f; if (diag && gc1 > r1g) v = MASK_BIAS; s[nt][3] = v + ma1;
        }

        // ---- online softmax ----
        float rx0 = -1e30f, rx1 = -1e30f;
        #pragma unroll
        for (int nt = 0; nt < 8; nt++) {
            rx0 = fmaxf(rx0, fmaxf(s[nt][0], s[nt][1]));
            rx1 = fmaxf(rx1, fmaxf(s[nt][2], s[nt][3]));
        }
        rx0 = fmaxf(rx0, __shfl_xor_sync(0xffffffffu, rx0, 1));
        rx0 = fmaxf(rx0, __shfl_xor_sync(0xffffffffu, rx0, 2));
        rx1 = fmaxf(rx1, __shfl_xor_sync(0xffffffffu, rx1, 1));
        rx1 = fmaxf(rx1, __shfl_xor_sync(0xffffffffu, rx1, 2));
        float m0n = fmaxf(m0, rx0), m1n = fmaxf(m1, rx1);
        float a0 = __expf(m0 - m0n), a1 = __expf(m1 - m1n);
        float sum0 = 0.f, sum1 = 0.f;
        #pragma unroll
        for (int nt = 0; nt < 8; nt++) {
            s[nt][0] = __expf(s[nt][0] - m0n);
            s[nt][1] = __expf(s[nt][1] - m0n);
            s[nt][2] = __expf(s[nt][2] - m1n);
            s[nt][3] = __expf(s[nt][3] - m1n);
            sum0 += s[nt][0] + s[nt][1];
            sum1 += s[nt][2] + s[nt][3];
        }
        sum0 += __shfl_xor_sync(0xffffffffu, sum0, 1);
        sum0 += __shfl_xor_sync(0xffffffffu, sum0, 2);
        sum1 += __shfl_xor_sync(0xffffffffu, sum1, 1);
        sum1 += __shfl_xor_sync(0xffffffffu, sum1, 2);
        l0 = l0 * a0 + sum0; l1 = l1 * a1 + sum1;
        m0 = m0n; m1 = m1n;
        #pragma unroll
        for (int nt = 0; nt < 8; nt++) {
            o[nt][0] *= a0; o[nt][1] *= a0;
            o[nt][2] *= a1; o[nt][3] *= a1;
        }

        // ---- P fragments (fp16 split hi/lo) ----
        uint32_t ph[4][4], pl[4][4];
        #pragma unroll
        for (int j = 0; j < 4; j++) {
            float* pa = s[2 * j];
            float* pb = s[2 * j + 1];
            ph[j][0] = pack_f16(pa[0], pa[1]);
            ph[j][1] = pack_f16(pa[2], pa[3]);
            ph[j][2] = pack_f16(pb[0], pb[1]);
            ph[j][3] = pack_f16(pb[2], pb[3]);
            __half2 h0 = *(__half2*)&ph[j][0];
            __half2 h1 = *(__half2*)&ph[j][1];
            __half2 h2 = *(__half2*)&ph[j][2];
            __half2 h3 = *(__half2*)&ph[j][3];
            pl[j][0] = pack_f16(pa[0] - __half2float(h0.x), pa[1] - __half2float(h0.y));
            pl[j][1] = pack_f16(pa[2] - __half2float(h1.x), pa[3] - __half2float(h1.y));
            pl[j][2] = pack_f16(pb[0] - __half2float(h2.x), pb[1] - __half2float(h2.y));
            pl[j][3] = pack_f16(pb[2] - __half2float(h3.x), pb[3] - __half2float(h3.y));
        }

        // ---- O += P V (fp16 x2), V frags via ldmatrix.trans ----
        #pragma unroll
        for (int ks = 0; ks < 4; ks++) {
            uint32_t vh[8][2];
            #pragma unroll
            for (int p2 = 0; p2 < 4; p2++) {
                int tile = lane >> 3, rown = lane & 7;
                int row = ks * 16 + (tile & 1) * 8 + rown;
                int col = (p2 * 2 + (tile >> 1)) * 8;
                uint32_t r4[4];
                ldmx4_trans(r4, smem_u32(&Vh[row][col]));
                vh[p2 * 2][0] = r4[0]; vh[p2 * 2][1] = r4[1];
                vh[p2 * 2 + 1][0] = r4[2]; vh[p2 * 2 + 1][1] = r4[3];
            }
            #pragma unroll
            for (int nt = 0; nt < 8; nt++) mma_f16(o[nt], ph[ks], vh[nt]);
            #pragma unroll
            for (int nt = 0; nt < 8; nt++) mma_f16(o[nt], pl[ks], vh[nt]);
        }
        __syncthreads();
    }

    // ---- normalize + split-write ctx (bf16 for x3 proj) ----
    float inv0 = 1.f / l0, inv1 = 1.f / l1;
    const size_t ro0 = (size_t)(b * TT + q0 + w * 16 + g) * DD + h * 64;
    const size_t ro1 = ro0 + (size_t)8 * DD;
    #pragma unroll
    for (int nt = 0; nt < 8; nt++) {
        int c = nt * 8 + 2 * t;
        float v0 = o[nt][0] * inv0, v1 = o[nt][1] * inv0;
        float v2 = o[nt][2] * inv1, v3 = o[nt][3] * inv1;
        __nv_bfloat16 h0,h1,h2,h3,l0b,l1b,l2b,l3b;
        split_bf16(v0,h0,l0b); split_bf16(v1,h1,l1b);
        split_bf16(v2,h2,l2b); split_bf16(v3,h3,l3b);
        *(__nv_bfloat162*)(ch + ro0 + c) = __nv_bfloat162{h0, h1};
        *(__nv_bfloat162*)(cl + ro0 + c) = __nv_bfloat162{l0b, l1b};
        *(__nv_bfloat162*)(ch + ro1 + c) = __nv_bfloat162{h2, h3};
        *(__nv_bfloat162*)(cl + ro1 + c) = __nv_bfloat162{l2b, l3b};
    }
}

// ---------------------------------------------------------------- launch
extern "C" void kernel_launch(void* const* d_in, const int* in_sizes, int n_in,
                              void* d_out, int out_size) {
    const float* emb   = (const float*)d_in[0];
    const float* amask = (const float*)d_in[1];
    const float* ln1w  = (const float*)d_in[2];
    const float* ln1b  = (const float*)d_in[3];
    const float* attnw = (const float*)d_in[4];
    const float* attnb = (const float*)d_in[5];
    const float* projw = (const float*)d_in[6];
    const float* projb = (const float*)d_in[7];
    const float* ln2w  = (const float*)d_in[8];
    const float* ln2b  = (const float*)d_in[9];
    const float* fcw   = (const float*)d_in[10];
    const float* fcb   = (const float*)d_in[11];
    const float* fcpw  = (const float*)d_in[12];
    const float* fcpb  = (const float*)d_in[13];
    const float* lnfw  = (const float*)d_in[14];
    const float* lnfb  = (const float*)d_in[15];
    float* out = (float*)d_out;

    float *H;
    __nv_bfloat16 *Ah, *Al, *Fh, *Fl, *Wh, *Wl;
    cudaGetSymbolAddress((void**)&H,   g_H);
    cudaGetSymbolAddress((void**)&Ah,  g_Ah);
    cudaGetSymbolAddress((void**)&Al,  g_Al);
    cudaGetSymbolAddress((void**)&Fh,  g_Fh);
    cudaGetSymbolAddress((void**)&Fl,  g_Fl);
    cudaGetSymbolAddress((void**)&Wh,  g_Wh);
    cudaGetSymbolAddress((void**)&Wl,  g_Wl);

    __half* AhH = (__half*)Ah;  __half* AlH = (__half*)Al;
    __half* FhH = (__half*)Fh;  __half* FlH = (__half*)Fl;
    __half* WhH = (__half*)Wh;

    cudaFuncSetAttribute(gemm_mma3,             cudaFuncAttributeMaxDynamicSharedMemorySize, GSMEM);
    cudaFuncSetAttribute(gemm_mma2<false,true >, cudaFuncAttributeMaxDynamicSharedMemorySize, GSMEM2);
    cudaFuncSetAttribute(gemm_mma2<true, false>, cudaFuncAttributeMaxDynamicSharedMemorySize, GSMEM2);

    const int n4 = (MROWS * DD) / 4;
    copy_kernel<<<(n4 + 255) / 256, 256>>>((const float4*)emb, (float4*)H, n4);

    for (int l = 0; l < LL; l++) {
        const size_t wq = (size_t)l * DD * 3 * DD;
        const size_t wp = (size_t)l * DD * DD;
        const size_t wf = (size_t)l * DD * II;
        const size_t wg = (size_t)l * II * DD;

        // --- attention ---
        ln_split_f16_kernel<<<MROWS, 256>>>(H, ln1w + l * DD, ln1b + l * DD, AhH, AlH);
        splitT_f16_kernel<<<dim3(3 * DD / 32, DD / 32), 256>>>(attnw + wq, WhH, DD, 3 * DD);
        gemm_mma2<false,true><<<dim3(3 * DD / 128, MROWS / 128), 256, GSMEM2>>>(
            AhH, AlH, WhH, attnb + (size_t)l * 3 * DD, FhH, FlH, 3 * DD, DD);
        attn_mma_kernel<<<dim3(TT / 64, HH, BB), 128>>>(FhH, FlH, amask, Ah, Al);
        splitT_kernel<<<dim3(DD / 32, DD / 32), 256>>>(projw + wp, Wh, Wl, DD, DD);
        gemm_mma3<<<dim3(DD / 128, MROWS / 128), 256, GSMEM>>>(
            Ah, Al, Wh, Wl, projb + (size_t)l * DD, H, H, DD, DD);

        // --- feed-forward ---
        ln_split_f16_kernel<<<MROWS, 256>>>(H, ln2w + l * DD, ln2b + l * DD, AhH, AlH);
        splitT_f16_kernel<<<dim3(II / 32, DD / 32), 256>>>(fcw + wf, WhH, DD, II);
        gemm_mma2<true,false><<<dim3(II / 128, MROWS / 128), 256, GSMEM2>>>(
            AhH, AlH, WhH, fcb + (size_t)l * II, Fh, Fl, II, DD);
        splitT_kernel<<<dim3(DD / 32, II / 32), 256>>>(fcpw + wg, Wh, Wl, II, DD);
        gemm_mma3<<<dim3(DD / 128, MROWS / 128), 256, GSMEM>>>(
            Fh, Fl, Wh, Wl, fcpb + (size_t)l * DD, H, H, DD, II);
    }
    ln_kernel<<<MROWS, 256>>>(H, lnfw, lnfb, out);
}

// round 16
// speedup vs baseline: 2.2691x; 1.1377x over previous
#include <cuda_runtime.h>
#include <cuda_bf16.h>
#include <cuda_fp16.h>
#include <math.h>
#include <stdint.h>

#define BB 2
#define TT 2048
#define DD 1024
#define HH 16
#define LL 8
#define II 4096
#define MROWS (BB*TT)          // 4096
#define MASK_BIAS (-10000.0f)

// -------- scratch (no allocations allowed) --------
static __device__ float  g_H [(size_t)MROWS*DD];     // residual stream (f32)
static __device__ __half g_Ah[(size_t)MROWS*II];     // activation split hi
static __device__ __half g_Al[(size_t)MROWS*II];     // activation split lo
static __device__ __half g_Fh[(size_t)MROWS*II];     // FF / QKV split hi
static __device__ __half g_Fl[(size_t)MROWS*II];     // FF / QKV split lo
static __device__ __half g_Wh[(size_t)II*DD];        // weight^T fp16 [N x K]

// ---------------------------------------------------------------- helpers
__device__ __forceinline__ uint32_t smem_u32(const void* p) {
    return (uint32_t)__cvta_generic_to_shared(p);
}

__device__ __forceinline__ void split_f16(float x, __half& h, __half& l) {
    h = __float2half_rn(x);
    l = __float2half_rn(x - __half2float(h));
}

__device__ __forceinline__ void mma_f16(float* c, const uint32_t* a, const uint32_t* b) {
    asm volatile(
        "mma.sync.aligned.m16n8k16.row.col.f32.f16.f16.f32 "
        "{%0,%1,%2,%3},{%4,%5,%6,%7},{%8,%9},{%0,%1,%2,%3};"
        : "+f"(c[0]), "+f"(c[1]), "+f"(c[2]), "+f"(c[3])
        : "r"(a[0]), "r"(a[1]), "r"(a[2]), "r"(a[3]), "r"(b[0]), "r"(b[1]));
}

__device__ __forceinline__ void cpasync16(uint32_t dst, const void* src) {
    asm volatile("cp.async.cg.shared.global [%0], [%1], 16;" :: "r"(dst), "l"(src));
}
__device__ __forceinline__ void cp_commit() { asm volatile("cp.async.commit_group;"); }
__device__ __forceinline__ void cp_wait1()  { asm volatile("cp.async.wait_group 1;"); }
__device__ __forceinline__ void cp_wait0()  { asm volatile("cp.async.wait_group 0;"); }

__device__ __forceinline__ void ldmx4(uint32_t* r, uint32_t saddr) {
    asm volatile("ldmatrix.sync.aligned.m8n8.x4.shared.b16 {%0,%1,%2,%3}, [%4];"
        : "=r"(r[0]), "=r"(r[1]), "=r"(r[2]), "=r"(r[3]) : "r"(saddr));
}
__device__ __forceinline__ void ldmx4_trans(uint32_t* r, uint32_t saddr) {
    asm volatile("ldmatrix.sync.aligned.m8n8.x4.trans.shared.b16 {%0,%1,%2,%3}, [%4];"
        : "=r"(r[0]), "=r"(r[1]), "=r"(r[2]), "=r"(r[3]) : "r"(saddr));
}

__device__ __forceinline__ uint32_t pack_f16(float x, float y) {
    __half2 v = __floats2half2_rn(x, y);
    return *(uint32_t*)&v;
}

// ---------------------------------------------------------------- copy
__global__ void copy_kernel(const float4* __restrict__ src, float4* __restrict__ dst, int n4) {
    int i = blockIdx.x * blockDim.x + threadIdx.x;
    if (i < n4) dst[i] = src[i];
}

// ---------------------------------------------------------------- layernorm core (256 thr, D=1024)
__device__ __forceinline__ float4 ln_core(const float* __restrict__ in,
                                          const float* __restrict__ w,
                                          const float* __restrict__ bsc, int row, int t) {
    const float4* x4 = (const float4*)(in + (size_t)row * DD);
    float4 v = x4[t];
    float s = v.x + v.y + v.z + v.w;
    float q = v.x*v.x + v.y*v.y + v.z*v.z + v.w*v.w;
    #pragma unroll
    for (int o = 16; o; o >>= 1) {
        s += __shfl_xor_sync(0xffffffffu, s, o);
        q += __shfl_xor_sync(0xffffffffu, q, o);
    }
    __shared__ float ss[8], sq[8];
    __shared__ float red[2];
    int wid = t >> 5, lane = t & 31;
    if (lane == 0) { ss[wid] = s; sq[wid] = q; }
    __syncthreads();
    if (t == 0) {
        float S = 0.f, Q = 0.f;
        #pragma unroll
        for (int i = 0; i < 8; i++) { S += ss[i]; Q += sq[i]; }
        float mean = S * (1.0f / DD);
        float var  = Q * (1.0f / DD) - mean * mean;
        red[0] = mean;
        red[1] = rsqrtf(var + 1e-5f);
    }
    __syncthreads();
    float mean = red[0], inv = red[1];
    float4 wv = ((const float4*)w)[t];
    float4 bv = ((const float4*)bsc)[t];
    float4 o;
    o.x = (v.x - mean) * inv * wv.x + bv.x;
    o.y = (v.y - mean) * inv * wv.y + bv.y;
    o.z = (v.z - mean) * inv * wv.z + bv.z;
    o.w = (v.w - mean) * inv * wv.w + bv.w;
    return o;
}

__global__ void ln_kernel(const float* __restrict__ in, const float* __restrict__ w,
                          const float* __restrict__ bsc, float* __restrict__ out) {
    int row = blockIdx.x, t = threadIdx.x;
    float4 o = ln_core(in, w, bsc, row, t);
    ((float4*)(out + (size_t)row * DD))[t] = o;
}

__global__ void ln_split_f16_kernel(const float* __restrict__ in, const float* __restrict__ w,
                                    const float* __restrict__ bsc,
                                    __half* __restrict__ oh, __half* __restrict__ ol) {
    int row = blockIdx.x, t = threadIdx.x;
    float4 o = ln_core(in, w, bsc, row, t);
    __half h0,h1,h2,h3,l0,l1,l2,l3;
    split_f16(o.x,h0,l0); split_f16(o.y,h1,l1); split_f16(o.z,h2,l2); split_f16(o.w,h3,l3);
    size_t idx = (size_t)row * DD + t * 4;
    *(__half2*)(oh + idx)     = __half2{h0,h1};
    *(__half2*)(oh + idx + 2) = __half2{h2,h3};
    *(__half2*)(ol + idx)     = __half2{l0,l1};
    *(__half2*)(ol + idx + 2) = __half2{l2,l3};
}

// ---------------------------------------------------------------- weight transpose (fp16)
// W: [K x N] f32 -> Th: [N x K] fp16
__global__ void splitT_f16_kernel(const float* __restrict__ W, __half* __restrict__ Th,
                                  int K, int N) {
    __shared__ float t[32][33];
    int k0 = blockIdx.y * 32, n0 = blockIdx.x * 32;
    int tx = threadIdx.x & 31, ty = threadIdx.x >> 5;
    #pragma unroll
    for (int i = 0; i < 4; i++) {
        int r = ty + i * 8;
        t[r][tx] = W[(size_t)(k0 + r) * N + n0 + tx];
    }
    __syncthreads();
    #pragma unroll
    for (int i = 0; i < 4; i++) {
        int r = ty + i * 8;
        Th[(size_t)(n0 + r) * K + k0 + tx] = __float2half_rn(t[tx][r]);
    }
}

// ---------------------------------------------------------------- fp16x2 GEMM (all 4 shapes)
// C[m][n] = sum_k A[m][k]*W[k][n] + bias (+res -> f32 C) (RELU opt; else split-f16 out)
#define SROWB   80                        // bytes per smem row (32 fp16 + 16 pad)
#define TILEB   (128 * SROWB)             // 10240 B
#define STAGEB2 (3 * TILEB)               // Ah, Al, Bh
#define GSMEM2  (2 * STAGEB2)             // 61440 B

template<bool RELU, bool RES>
__global__ __launch_bounds__(256, 2)
void gemm_mma2(const __half* __restrict__ Ah, const __half* __restrict__ Al,
               const __half* __restrict__ Bh,
               const float* __restrict__ bias, const float* __restrict__ res,
               float* __restrict__ C,
               __half* __restrict__ Ch, __half* __restrict__ Cl, int N, int K) {
    extern __shared__ char sm[];
    const int tid = threadIdx.x, lane = tid & 31, wid = tid >> 5;
    const int g = lane >> 2, t = lane & 3;
    const int warpM = (wid >> 2) * 64, warpN = (wid & 3) * 32;
    const int M0 = blockIdx.y * 128, N0 = blockIdx.x * 128;

    const __half* srcs[3] = {Ah, Al, Bh};
    const int bases[3] = {M0, M0, N0};

    auto issue = [&](int c, int s) {
        const int k0 = c << 5;
        #pragma unroll
        for (int arr = 0; arr < 3; arr++) {
            char* dstb = sm + s * STAGEB2 + arr * TILEB;
            const __half* srcb = srcs[arr] + (size_t)bases[arr] * K + k0;
            #pragma unroll
            for (int i = 0; i < 2; i++) {
                int cc = i * 256 + tid;
                int r = cc >> 2, j = cc & 3;
                cpasync16(smem_u32(dstb + r * SROWB + j * 16),
                          srcb + (size_t)r * K + j * 8);
            }
        }
    };

    float acc[4][4][4];
    #pragma unroll
    for (int i = 0; i < 4; i++)
        #pragma unroll
        for (int j = 0; j < 4; j++)
            #pragma unroll
            for (int r = 0; r < 4; r++) acc[i][j][r] = 0.f;

    const int nch = K >> 5;
    issue(0, 0); cp_commit();

    const int arow_l = lane & 15;
    const int acol_l = (lane >> 4) << 3;
    const int brow_l = (lane & 7) + ((lane >> 4) << 3);
    const int bcol_l = ((lane >> 3) & 1) << 3;

    for (int c = 0; c < nch; ++c) {
        if (c + 1 < nch) { issue(c + 1, (c + 1) & 1); cp_commit(); cp_wait1(); }
        else cp_wait0();
        __syncthreads();

        const uint32_t sb = smem_u32(sm + (c & 1) * STAGEB2);
        #pragma unroll
        for (int ks = 0; ks < 2; ks++) {
            const int kb = ks * 16;
            uint32_t ah[4][4], al[4][4];
            #pragma unroll
            for (int fm = 0; fm < 4; fm++) {
                uint32_t ad = sb + (uint32_t)(warpM + fm * 16 + arow_l) * SROWB
                                 + (uint32_t)(kb + acol_l) * 2;
                ldmx4(ah[fm], ad);
                ldmx4(al[fm], ad + TILEB);
            }
            uint32_t bh[4][2];
            #pragma unroll
            for (int fp = 0; fp < 2; fp++) {
                uint32_t bd = sb + 2 * TILEB
                                 + (uint32_t)(warpN + fp * 16 + brow_l) * SROWB
                                 + (uint32_t)(kb + bcol_l) * 2;
                uint32_t r4[4];
                ldmx4(r4, bd);
                bh[2*fp][0] = r4[0]; bh[2*fp][1] = r4[1];
                bh[2*fp+1][0] = r4[2]; bh[2*fp+1][1] = r4[3];
            }
            #pragma unroll
            for (int fm = 0; fm < 4; fm++)
                #pragma unroll
                for (int fn = 0; fn < 4; fn++)
                    mma_f16(acc[fm][fn], ah[fm], bh[fn]);
            #pragma unroll
            for (int fm = 0; fm < 4; fm++)
                #pragma unroll
                for (int fn = 0; fn < 4; fn++)
                    mma_f16(acc[fm][fn], al[fm], bh[fn]);
        }
        __syncthreads();
    }

    #pragma unroll
    for (int fm = 0; fm < 4; fm++) {
        const int rbase = M0 + warpM + fm * 16 + g;
        #pragma unroll
        for (int half = 0; half < 2; half++) {
            const int row = rbase + half * 8;
            #pragma unroll
            for (int fn = 0; fn < 4; fn++) {
                const int col = N0 + warpN + fn * 8 + 2 * t;
                float v0 = acc[fm][fn][half * 2 + 0] + __ldg(&bias[col]);
                float v1 = acc[fm][fn][half * 2 + 1] + __ldg(&bias[col + 1]);
                if (RELU) { v0 = fmaxf(v0, 0.f); v1 = fmaxf(v1, 0.f); }
                if (RES) {
                    float2 rv = *(const float2*)(res + (size_t)row * N + col);
                    v0 += rv.x; v1 += rv.y;
                    *(float2*)(C + (size_t)row * N + col) = make_float2(v0, v1);
                } else {
                    __half h0,h1,l0,l1;
                    split_f16(v0, h0, l0);
                    split_f16(v1, h1, l1);
                    *(__half2*)(Ch + (size_t)row * N + col) = __half2{h0, h1};
                    *(__half2*)(Cl + (size_t)row * N + col) = __half2{l0, l1};
                }
            }
        }
    }
}

// ---------------------------------------------------------------- tensor-core flash attention (fp16 x2)
// grid (T/64, H, B), 128 thr. BQ=64, BK=64, hd=64.
// qkv split fp16 (Q hi+lo, K/V hi only). Output ctx split fp16 into ch/cl.
#define KSTR 72

__global__ __launch_bounds__(128)
void attn_mma_kernel(const __half* __restrict__ qh_g, const __half* __restrict__ ql_g,
                     const float* __restrict__ amask,
                     __half* __restrict__ ch, __half* __restrict__ cl) {
    const int q0 = blockIdx.x * 64;
    const int h = blockIdx.y, b = blockIdx.z;
    const int tid = threadIdx.x, lane = tid & 31, w = tid >> 5;
    const int g = lane >> 2, t = lane & 3;

    __shared__ alignas(16) __half Kh[64][KSTR];
    __shared__ alignas(16) __half Vh[64][KSTR];
    __shared__ float madd[64];

    // ---- Q fragments (once per block), rows w*16+g / +8 ----
    uint32_t qfh[4][4], qfl[4][4];
    {
        const size_t r0 = ((size_t)(b * TT + q0 + w * 16 + g)) * (3 * DD) + h * 64;
        const size_t r1 = r0 + (size_t)8 * (3 * DD);
        #pragma unroll
        for (int ks = 0; ks < 4; ks++) {
            int c = ks * 16 + 2 * t;
            qfh[ks][0] = *(const uint32_t*)(qh_g + r0 + c);
            qfh[ks][1] = *(const uint32_t*)(qh_g + r1 + c);
            qfh[ks][2] = *(const uint32_t*)(qh_g + r0 + c + 8);
            qfh[ks][3] = *(const uint32_t*)(qh_g + r1 + c + 8);
            qfl[ks][0] = *(const uint32_t*)(ql_g + r0 + c);
            qfl[ks][1] = *(const uint32_t*)(ql_g + r1 + c);
            qfl[ks][2] = *(const uint32_t*)(ql_g + r0 + c + 8);
            qfl[ks][3] = *(const uint32_t*)(ql_g + r1 + c + 8);
        }
    }

    float o[8][4];
    #pragma unroll
    for (int i = 0; i < 8; i++)
        #pragma unroll
        for (int j = 0; j < 4; j++) o[i][j] = 0.f;
    float m0 = -1e30f, m1 = -1e30f, l0 = 0.f, l1 = 0.f;

    for (int k0 = 0; k0 <= q0; k0 += 64) {
        {
            const size_t gk = ((size_t)(b * TT + k0)) * (3 * DD) + DD + h * 64;
            const size_t gv = gk + DD;
            #pragma unroll
            for (int i = 0; i < 4; i++) {
                int cc = i * 128 + tid;
                int r = cc >> 3, j8 = (cc & 7) * 8;
                size_t rowoff = (size_t)r * (3 * DD) + j8;
                cpasync16(smem_u32(&Kh[r][j8]), qh_g + gk + rowoff);
                cpasync16(smem_u32(&Vh[r][j8]), qh_g + gv + rowoff);
            }
            cp_commit();
        }
        if (tid < 64) madd[tid] = (1.0f - __ldg(&amask[b * TT + k0 + tid])) * MASK_BIAS;
        cp_wait0();
        __syncthreads();

        // ---- S = Q K^T (fp16 x2) ----
        float s[8][4];
        #pragma unroll
        for (int i = 0; i < 8; i++)
            #pragma unroll
            for (int j = 0; j < 4; j++) s[i][j] = 0.f;
        #pragma unroll
        for (int ks = 0; ks < 4; ks++) {
            const int kb = ks * 16 + 2 * t;
            uint32_t bh[8][2];
            #pragma unroll
            for (int nt = 0; nt < 8; nt++) {
                const __half* rp = &Kh[nt * 8 + g][kb];
                bh[nt][0] = *(const uint32_t*)(rp);
                bh[nt][1] = *(const uint32_t*)(rp + 8);
            }
            #pragma unroll
            for (int nt = 0; nt < 8; nt++) mma_f16(s[nt], qfh[ks], bh[nt]);
            #pragma unroll
            for (int nt = 0; nt < 8; nt++) mma_f16(s[nt], qfl[ks], bh[nt]);
        }

        // ---- scale + masks ----
        const int r0g = q0 + w * 16 + g, r1g = r0g + 8;
        const bool diag = (k0 == q0);
        #pragma unroll
        for (int nt = 0; nt < 8; nt++) {
            int c0 = nt * 8 + 2 * t, c1 = c0 + 1;
            float ma0 = madd[c0], ma1 = madd[c1];
            int gc0 = k0 + c0, gc1 = k0 + c1;
            float v;
            v = s[nt][0] * 0.125f; if (diag && gc0 > r0g) v = MASK_BIAS; s[nt][0] = v + ma0;
            v = s[nt][1] * 0.125f; if (diag && gc1 > r0g) v = MASK_BIAS; s[nt][1] = v + ma1;
            v = s[nt][2] * 0.125f; if (diag && gc0 > r1g) v = MASK_BIAS; s[nt][2] = v + ma0;
            v = s[nt][3] * 0.125f; if (diag && gc1 > r1g) v = MASK_BIAS; s[nt][3] = v + ma1;
        }

        // ---- online softmax ----
        float rx0 = -1e30f, rx1 = -1e30f;
        #pragma unroll
        for (int nt = 0; nt < 8; nt++) {
            rx0 = fmaxf(rx0, fmaxf(s[nt][0], s[nt][1]));
            rx1 = fmaxf(rx1, fmaxf(s[nt][2], s[nt][3]));
        }
        rx0 = fmaxf(rx0, __shfl_xor_sync(0xffffffffu, rx0, 1));
        rx0 = fmaxf(rx0, __shfl_xor_sync(0xffffffffu, rx0, 2));
        rx1 = fmaxf(rx1, __shfl_xor_sync(0xffffffffu, rx1, 1));
        rx1 = fmaxf(rx1, __shfl_xor_sync(0xffffffffu, rx1, 2));
        float m0n = fmaxf(m0, rx0), m1n = fmaxf(m1, rx1);
        float a0 = __expf(m0 - m0n), a1 = __expf(m1 - m1n);
        float sum0 = 0.f, sum1 = 0.f;
        #pragma unroll
        for (int nt = 0; nt < 8; nt++) {
            s[nt][0] = __expf(s[nt][0] - m0n);
            s[nt][1] = __expf(s[nt][1] - m0n);
            s[nt][2] = __expf(s[nt][2] - m1n);
            s[nt][3] = __expf(s[nt][3] - m1n);
            sum0 += s[nt][0] + s[nt][1];
            sum1 += s[nt][2] + s[nt][3];
        }
        sum0 += __shfl_xor_sync(0xffffffffu, sum0, 1);
        sum0 += __shfl_xor_sync(0xffffffffu, sum0, 2);
        sum1 += __shfl_xor_sync(0xffffffffu, sum1, 1);
        sum1 += __shfl_xor_sync(0xffffffffu, sum1, 2);
        l0 = l0 * a0 + sum0; l1 = l1 * a1 + sum1;
        m0 = m0n; m1 = m1n;
        #pragma unroll
        for (int nt = 0; nt < 8; nt++) {
            o[nt][0] *= a0; o[nt][1] *= a0;
            o[nt][2] *= a1; o[nt][3] *= a1;
        }

        // ---- P fragments (fp16 split hi/lo) ----
        uint32_t ph[4][4], pl[4][4];
        #pragma unroll
        for (int j = 0; j < 4; j++) {
            float* pa = s[2 * j];
            float* pb = s[2 * j + 1];
            ph[j][0] = pack_f16(pa[0], pa[1]);
            ph[j][1] = pack_f16(pa[2], pa[3]);
            ph[j][2] = pack_f16(pb[0], pb[1]);
            ph[j][3] = pack_f16(pb[2], pb[3]);
            __half2 h0 = *(__half2*)&ph[j][0];
            __half2 h1 = *(__half2*)&ph[j][1];
            __half2 h2 = *(__half2*)&ph[j][2];
            __half2 h3 = *(__half2*)&ph[j][3];
            pl[j][0] = pack_f16(pa[0] - __half2float(h0.x), pa[1] - __half2float(h0.y));
            pl[j][1] = pack_f16(pa[2] - __half2float(h1.x), pa[3] - __half2float(h1.y));
            pl[j][2] = pack_f16(pb[0] - __half2float(h2.x), pb[1] - __half2float(h2.y));
            pl[j][3] = pack_f16(pb[2] - __half2float(h3.x), pb[3] - __half2float(h3.y));
        }

        // ---- O += P V (fp16 x2), V frags via ldmatrix.trans ----
        #pragma unroll
        for (int ks = 0; ks < 4; ks++) {
            uint32_t vh[8][2];
            #pragma unroll
            for (int p2 = 0; p2 < 4; p2++) {
                int tile = lane >> 3, rown = lane & 7;
                int row = ks * 16 + (tile & 1) * 8 + rown;
                int col = (p2 * 2 + (tile >> 1)) * 8;
                uint32_t r4[4];
                ldmx4_trans(r4, smem_u32(&Vh[row][col]));
                vh[p2 * 2][0] = r4[0]; vh[p2 * 2][1] = r4[1];
                vh[p2 * 2 + 1][0] = r4[2]; vh[p2 * 2 + 1][1] = r4[3];
            }
            #pragma unroll
            for (int nt = 0; nt < 8; nt++) mma_f16(o[nt], ph[ks], vh[nt]);
            #pragma unroll
            for (int nt = 0; nt < 8; nt++) mma_f16(o[nt], pl[ks], vh[nt]);
        }
        __syncthreads();
    }

    // ---- normalize + split-write ctx (fp16) ----
    float inv0 = 1.f / l0, inv1 = 1.f / l1;
    const size_t ro0 = (size_t)(b * TT + q0 + w * 16 + g) * DD + h * 64;
    const size_t ro1 = ro0 + (size_t)8 * DD;
    #pragma unroll
    for (int nt = 0; nt < 8; nt++) {
        int c = nt * 8 + 2 * t;
        float v0 = o[nt][0] * inv0, v1 = o[nt][1] * inv0;
        float v2 = o[nt][2] * inv1, v3 = o[nt][3] * inv1;
        __half h0,h1,h2,h3,l0b,l1b,l2b,l3b;
        split_f16(v0,h0,l0b); split_f16(v1,h1,l1b);
        split_f16(v2,h2,l2b); split_f16(v3,h3,l3b);
        *(__half2*)(ch + ro0 + c) = __half2{h0, h1};
        *(__half2*)(cl + ro0 + c) = __half2{l0b, l1b};
        *(__half2*)(ch + ro1 + c) = __half2{h2, h3};
        *(__half2*)(cl + ro1 + c) = __half2{l2b, l3b};
    }
}

// ---------------------------------------------------------------- launch
extern "C" void kernel_launch(void* const* d_in, const int* in_sizes, int n_in,
                              void* d_out, int out_size) {
    const float* emb   = (const float*)d_in[0];
    const float* amask = (const float*)d_in[1];
    const float* ln1w  = (const float*)d_in[2];
    const float* ln1b  = (const float*)d_in[3];
    const float* attnw = (const float*)d_in[4];
    const float* attnb = (const float*)d_in[5];
    const float* projw = (const float*)d_in[6];
    const float* projb = (const float*)d_in[7];
    const float* ln2w  = (const float*)d_in[8];
    const float* ln2b  = (const float*)d_in[9];
    const float* fcw   = (const float*)d_in[10];
    const float* fcb   = (const float*)d_in[11];
    const float* fcpw  = (const float*)d_in[12];
    const float* fcpb  = (const float*)d_in[13];
    const float* lnfw  = (const float*)d_in[14];
    const float* lnfb  = (const float*)d_in[15];
    float* out = (float*)d_out;

    float *H;
    __half *Ah, *Al, *Fh, *Fl, *Wh;
    cudaGetSymbolAddress((void**)&H,  g_H);
    cudaGetSymbolAddress((void**)&Ah, g_Ah);
    cudaGetSymbolAddress((void**)&Al, g_Al);
    cudaGetSymbolAddress((void**)&Fh, g_Fh);
    cudaGetSymbolAddress((void**)&Fl, g_Fl);
    cudaGetSymbolAddress((void**)&Wh, g_Wh);

    cudaFuncSetAttribute(gemm_mma2<false,false>, cudaFuncAttributeMaxDynamicSharedMemorySize, GSMEM2);
    cudaFuncSetAttribute(gemm_mma2<false,true >, cudaFuncAttributeMaxDynamicSharedMemorySize, GSMEM2);
    cudaFuncSetAttribute(gemm_mma2<true, false>, cudaFuncAttributeMaxDynamicSharedMemorySize, GSMEM2);

    const int n4 = (MROWS * DD) / 4;
    copy_kernel<<<(n4 + 255) / 256, 256>>>((const float4*)emb, (float4*)H, n4);

    for (int l = 0; l < LL; l++) {
        const size_t wq = (size_t)l * DD * 3 * DD;
        const size_t wp = (size_t)l * DD * DD;
        const size_t wf = (size_t)l * DD * II;
        const size_t wg = (size_t)l * II * DD;

        // --- attention ---
        ln_split_f16_kernel<<<MROWS, 256>>>(H, ln1w + l * DD, ln1b + l * DD, Ah, Al);
        splitT_f16_kernel<<<dim3(3 * DD / 32, DD / 32), 256>>>(attnw + wq, Wh, DD, 3 * DD);
        gemm_mma2<false,false><<<dim3(3 * DD / 128, MROWS / 128), 256, GSMEM2>>>(
            Ah, Al, Wh, attnb + (size_t)l * 3 * DD, nullptr, nullptr, Fh, Fl, 3 * DD, DD);
        attn_mma_kernel<<<dim3(TT / 64, HH, BB), 128>>>(Fh, Fl, amask, Ah, Al);
        splitT_f16_kernel<<<dim3(DD / 32, DD / 32), 256>>>(projw + wp, Wh, DD, DD);
        gemm_mma2<false,true><<<dim3(DD / 128, MROWS / 128), 256, GSMEM2>>>(
            Ah, Al, Wh, projb + (size_t)l * DD, H, H, nullptr, nullptr, DD, DD);

        // --- feed-forward ---
        ln_split_f16_kernel<<<MROWS, 256>>>(H, ln2w + l * DD, ln2b + l * DD, Ah, Al);
        splitT_f16_kernel<<<dim3(II / 32, DD / 32), 256>>>(fcw + wf, Wh, DD, II);
        gemm_mma2<true,false><<<dim3(II / 128, MROWS / 128), 256, GSMEM2>>>(
            Ah, Al, Wh, fcb + (size_t)l * II, nullptr, nullptr, Fh, Fl, II, DD);
        splitT_f16_kernel<<<dim3(DD / 32, II / 32), 256>>>(fcpw + wg, Wh, II, DD);
        gemm_mma2<false,true><<<dim3(DD / 128, MROWS / 128), 256, GSMEM2>>>(
            Fh, Fl, Wh, fcpb + (size_t)l * DD, H, H, nullptr, nullptr, DD, II);
    }
    ln_kernel<<<MROWS, 256>>>(H, lnfw, lnfb, out);
}